// round 1
// baseline (speedup 1.0000x reference)
#include <cuda_runtime.h>
#include <math.h>
#include <stdint.h>

// Problem dims
#define BB   8
#define TT   128
#define NN   64
#define KH   8
#define DH   64
#define DD   512
#define MTOT (BB*TT*NN)      // 65536
#define KDIM_QKV 1536
#define KDIM_PROJ 512

// Scratch (device globals — allocation-free rule)
__device__ float g_q[(size_t)BB*NN*KH*TT*DH];     // [B,N,K,T,d]
__device__ float g_k[(size_t)BB*NN*KH*TT*DH];
__device__ float g_v[(size_t)BB*NN*KH*TT*DH];
__device__ float g_attn[(size_t)MTOT*DD];         // [B,T,N,D] row-major

// ---------------------------------------------------------------------------
// Fused QKV projection: out = relu([X|STE] @ W^T + b), stored as [B,N,K,T,d]
// Tile: 128x128, BK=16, 256 threads, 8x8 per thread.
// ---------------------------------------------------------------------------
__global__ __launch_bounds__(256) void qkv_gemm(
    const float* __restrict__ X, const float* __restrict__ STE,
    const float* __restrict__ Wq, const float* __restrict__ Wk, const float* __restrict__ Wv,
    const float* __restrict__ bq, const float* __restrict__ bk, const float* __restrict__ bv)
{
    const int z = blockIdx.z;
    const float* __restrict__ W    = (z == 0) ? Wq : (z == 1) ? Wk : Wv;
    const float* __restrict__ bias = (z == 0) ? bq : (z == 1) ? bk : bv;
    float* __restrict__ out        = (z == 0) ? g_q : (z == 1) ? g_k : g_v;

    __shared__ float As[16 * 132];
    __shared__ float Bs[16 * 132];

    const int tid = threadIdx.x;
    const int m0  = blockIdx.y * 128;
    const int n0  = blockIdx.x * 128;

    const int lr = tid >> 2;   // 0..63
    const int c4 = tid & 3;    // 0..3
    const int tx = tid & 15;
    const int ty = tid >> 4;

    float acc[8][8];
    #pragma unroll
    for (int i = 0; i < 8; ++i)
        #pragma unroll
        for (int j = 0; j < 8; ++j) acc[i][j] = 0.f;

    for (int kt = 0; kt < KDIM_QKV / 16; ++kt) {
        const int col = kt * 16 + c4 * 4;
        // A tile: H = concat(X[...512], STE[...1024]); each 16-col tile lies in one source
        #pragma unroll
        for (int i = 0; i < 2; ++i) {
            const int rl = lr + i * 64;
            const size_t r = (size_t)(m0 + rl);
            float4 a;
            if (col < 512) a = *(const float4*)(X   + r * 512  + col);
            else           a = *(const float4*)(STE + r * 1024 + (col - 512));
            As[(c4*4+0)*132 + rl] = a.x;
            As[(c4*4+1)*132 + rl] = a.y;
            As[(c4*4+2)*132 + rl] = a.z;
            As[(c4*4+3)*132 + rl] = a.w;
        }
        // B tile: Bs[k][o] = W[o, k]
        #pragma unroll
        for (int i = 0; i < 2; ++i) {
            const int ol = lr + i * 64;
            float4 w = *(const float4*)(W + (size_t)(n0 + ol) * KDIM_QKV + kt * 16 + c4 * 4);
            Bs[(c4*4+0)*132 + ol] = w.x;
            Bs[(c4*4+1)*132 + ol] = w.y;
            Bs[(c4*4+2)*132 + ol] = w.z;
            Bs[(c4*4+3)*132 + ol] = w.w;
        }
        __syncthreads();
        #pragma unroll
        for (int kk = 0; kk < 16; ++kk) {
            float a[8], b[8];
            *(float4*)&a[0] = *(const float4*)&As[kk*132 + ty*8];
            *(float4*)&a[4] = *(const float4*)&As[kk*132 + ty*8 + 4];
            *(float4*)&b[0] = *(const float4*)&Bs[kk*132 + tx*8];
            *(float4*)&b[4] = *(const float4*)&Bs[kk*132 + tx*8 + 4];
            #pragma unroll
            for (int i = 0; i < 8; ++i)
                #pragma unroll
                for (int j = 0; j < 8; ++j)
                    acc[i][j] += a[i] * b[j];
        }
        __syncthreads();
    }

    // Epilogue: bias + relu, scatter to [B,N,K,T,d]
    const int o0   = n0 + tx * 8;
    const int head = o0 >> 6;
    const int jj   = o0 & 63;
    float bv8[8];
    #pragma unroll
    for (int j = 0; j < 8; ++j) bv8[j] = bias[o0 + j];

    #pragma unroll
    for (int i = 0; i < 8; ++i) {
        const int R  = m0 + ty * 8 + i;
        const int b_ = R >> 13;          // / (T*N)
        const int t_ = (R >> 6) & 127;
        const int n_ = R & 63;
        float v[8];
        #pragma unroll
        for (int j = 0; j < 8; ++j) {
            float x = acc[i][j] + bv8[j];
            v[j] = x > 0.f ? x : 0.f;
        }
        const size_t idx = ((((size_t)b_ * NN + n_) * KH + head) * TT + t_) * DH + jj;
        *(float4*)(out + idx)     = make_float4(v[0], v[1], v[2], v[3]);
        *(float4*)(out + idx + 4) = make_float4(v[4], v[5], v[6], v[7]);
    }
}

// ---------------------------------------------------------------------------
// Attention: one block per (b, n, head); 128 threads, one query row each.
// Writes directly into [B,T,N,D] layout so the output projection is a plain GEMM.
// ---------------------------------------------------------------------------
__global__ __launch_bounds__(128) void attn_kernel()
{
    extern __shared__ float sm[];
    float* Ks = sm;                 // 128*64
    float* Vs = sm + 8192;          // 128*64
    float* Ss = sm + 16384;         // 128*129 (padded)

    const int head = blockIdx.x;
    const int n    = blockIdx.y;
    const int b    = blockIdx.z;
    const size_t base = ((size_t)(b * NN + n) * KH + head) * (TT * DH);

    const int tid = threadIdx.x;    // == query row t
    const int t   = tid;

    // Cooperative K/V loads
    const float4* k4 = (const float4*)(g_k + base);
    const float4* v4 = (const float4*)(g_v + base);
    float4* Ks4 = (float4*)Ks;
    float4* Vs4 = (float4*)Vs;
    #pragma unroll 4
    for (int i = tid; i < (TT * DH) / 4; i += 128) {
        Ks4[i] = k4[i];
        Vs4[i] = v4[i];
    }

    // This thread's q row into registers
    float4 q[16];
    const float4* q4 = (const float4*)(g_q + base + (size_t)t * DH);
    #pragma unroll
    for (int i = 0; i < 16; ++i) q[i] = q4[i];

    __syncthreads();

    // Pass 1: scores (causal) + row max
    float m = -INFINITY;
    for (int s = 0; s <= t; ++s) {
        const float4* kr = (const float4*)(Ks + s * DH);
        float a0 = 0.f, a1 = 0.f, a2 = 0.f, a3 = 0.f;
        #pragma unroll
        for (int i = 0; i < 16; ++i) {
            float4 kv = kr[i];
            a0 += q[i].x * kv.x;
            a1 += q[i].y * kv.y;
            a2 += q[i].z * kv.z;
            a3 += q[i].w * kv.w;
        }
        const float sc = (a0 + a1 + a2 + a3) * 0.125f;
        Ss[t * 129 + s] = sc;
        m = fmaxf(m, sc);
    }

    // Pass 2: exp + sum
    float l = 0.f;
    for (int s = 0; s <= t; ++s) {
        const float p = __expf(Ss[t * 129 + s] - m);
        Ss[t * 129 + s] = p;
        l += p;
    }
    const float inv = 1.f / l;

    // Pass 3: O = P @ V, write to g_attn[B,T,N,D] at channel head*64
    const size_t row_off = ((size_t)(b * TT + t) * NN + n) * DD + head * DH;
    #pragma unroll
    for (int j0 = 0; j0 < DH; j0 += 32) {
        float acc[32];
        #pragma unroll
        for (int c = 0; c < 32; ++c) acc[c] = 0.f;
        for (int s = 0; s <= t; ++s) {
            const float p = Ss[t * 129 + s];
            const float4* vr = (const float4*)(Vs + s * DH + j0);
            #pragma unroll
            for (int c = 0; c < 8; ++c) {
                float4 vv = vr[c];
                acc[c*4+0] += p * vv.x;
                acc[c*4+1] += p * vv.y;
                acc[c*4+2] += p * vv.z;
                acc[c*4+3] += p * vv.w;
            }
        }
        #pragma unroll
        for (int c = 0; c < 8; ++c) {
            float4 r = make_float4(acc[c*4+0]*inv, acc[c*4+1]*inv, acc[c*4+2]*inv, acc[c*4+3]*inv);
            *(float4*)(g_attn + row_off + j0 + c * 4) = r;
        }
    }
}

// ---------------------------------------------------------------------------
// Output projection: d_out = relu(g_attn @ Wo^T + bo), row-major [M, 512]
// ---------------------------------------------------------------------------
__global__ __launch_bounds__(256) void proj_gemm(
    const float* __restrict__ Wo, const float* __restrict__ bo, float* __restrict__ out)
{
    __shared__ float As[16 * 132];
    __shared__ float Bs[16 * 132];

    const int tid = threadIdx.x;
    const int m0  = blockIdx.y * 128;
    const int n0  = blockIdx.x * 128;

    const int lr = tid >> 2;
    const int c4 = tid & 3;
    const int tx = tid & 15;
    const int ty = tid >> 4;

    float acc[8][8];
    #pragma unroll
    for (int i = 0; i < 8; ++i)
        #pragma unroll
        for (int j = 0; j < 8; ++j) acc[i][j] = 0.f;

    for (int kt = 0; kt < KDIM_PROJ / 16; ++kt) {
        const int col = kt * 16 + c4 * 4;
        #pragma unroll
        for (int i = 0; i < 2; ++i) {
            const int rl = lr + i * 64;
            float4 a = *(const float4*)(g_attn + (size_t)(m0 + rl) * DD + col);
            As[(c4*4+0)*132 + rl] = a.x;
            As[(c4*4+1)*132 + rl] = a.y;
            As[(c4*4+2)*132 + rl] = a.z;
            As[(c4*4+3)*132 + rl] = a.w;
        }
        #pragma unroll
        for (int i = 0; i < 2; ++i) {
            const int ol = lr + i * 64;
            float4 w = *(const float4*)(Wo + (size_t)(n0 + ol) * KDIM_PROJ + col);
            Bs[(c4*4+0)*132 + ol] = w.x;
            Bs[(c4*4+1)*132 + ol] = w.y;
            Bs[(c4*4+2)*132 + ol] = w.z;
            Bs[(c4*4+3)*132 + ol] = w.w;
        }
        __syncthreads();
        #pragma unroll
        for (int kk = 0; kk < 16; ++kk) {
            float a[8], b[8];
            *(float4*)&a[0] = *(const float4*)&As[kk*132 + ty*8];
            *(float4*)&a[4] = *(const float4*)&As[kk*132 + ty*8 + 4];
            *(float4*)&b[0] = *(const float4*)&Bs[kk*132 + tx*8];
            *(float4*)&b[4] = *(const float4*)&Bs[kk*132 + tx*8 + 4];
            #pragma unroll
            for (int i = 0; i < 8; ++i)
                #pragma unroll
                for (int j = 0; j < 8; ++j)
                    acc[i][j] += a[i] * b[j];
        }
        __syncthreads();
    }

    const int o0 = n0 + tx * 8;
    float bv8[8];
    #pragma unroll
    for (int j = 0; j < 8; ++j) bv8[j] = bo[o0 + j];

    #pragma unroll
    for (int i = 0; i < 8; ++i) {
        const size_t R = (size_t)(m0 + ty * 8 + i);
        float v[8];
        #pragma unroll
        for (int j = 0; j < 8; ++j) {
            float x = acc[i][j] + bv8[j];
            v[j] = x > 0.f ? x : 0.f;
        }
        *(float4*)(out + R * DD + o0)     = make_float4(v[0], v[1], v[2], v[3]);
        *(float4*)(out + R * DD + o0 + 4) = make_float4(v[4], v[5], v[6], v[7]);
    }
}

// ---------------------------------------------------------------------------
extern "C" void kernel_launch(void* const* d_in, const int* in_sizes, int n_in,
                              void* d_out, int out_size)
{
    const float* X   = (const float*)d_in[0];
    const float* STE = (const float*)d_in[1];
    const float* Wq  = (const float*)d_in[2];
    const float* bq  = (const float*)d_in[3];
    const float* Wk  = (const float*)d_in[4];
    const float* bk  = (const float*)d_in[5];
    const float* Wv  = (const float*)d_in[6];
    const float* bv  = (const float*)d_in[7];
    const float* Wo  = (const float*)d_in[8];
    const float* bo  = (const float*)d_in[9];
    float* out = (float*)d_out;

    // QKV: grid (Ntiles=4, Mtiles=512, qkv=3)
    qkv_gemm<<<dim3(4, 512, 3), 256>>>(X, STE, Wq, Wk, Wv, bq, bk, bv);

    // Attention: 4096 blocks (head, n, b), 131584 B dynamic smem
    const int attn_smem = (16384 + 128 * 129) * (int)sizeof(float);
    cudaFuncSetAttribute(attn_kernel, cudaFuncAttributeMaxDynamicSharedMemorySize, attn_smem);
    attn_kernel<<<dim3(KH, NN, BB), 128, attn_smem>>>();

    // Output projection: grid (4, 512)
    proj_gemm<<<dim3(4, 512), 256>>>(Wo, bo, out);
}

// round 3
// speedup vs baseline: 2.5729x; 2.5729x over previous
#include <cuda_runtime.h>
#include <math.h>
#include <stdint.h>

// Problem dims
#define BB   8
#define TT   128
#define NN   64
#define KH   8
#define DH   64
#define DD   512

// Scratch (device globals — allocation-free rule)
__device__ float g_q[(size_t)BB*NN*KH*TT*DH];     // [B,N,K,T,d]
__device__ float g_k[(size_t)BB*NN*KH*TT*DH];
__device__ float g_v[(size_t)BB*NN*KH*TT*DH];
__device__ float g_attn[(size_t)BB*TT*NN*DD];     // [B,T,N,D] row-major

// ---------------------------------------------------------------------------
// Helpers
// ---------------------------------------------------------------------------
__device__ __forceinline__ uint32_t smem_u32(const void* p) {
    uint32_t a;
    asm("{ .reg .u64 t; cvta.to.shared.u64 t, %1; cvt.u32.u64 %0, t; }" : "=r"(a) : "l"(p));
    return a;
}
__device__ __forceinline__ uint32_t f2tf32(float x) {
    uint32_t u;
    asm("cvt.rna.tf32.f32 %0, %1;" : "=r"(u) : "f"(x));
    return u;
}
#define SWZ(o) ((o) ^ (((o) >> 3) & 0x70))

#define LDMATRIX_X4(r0, r1, r2, r3, addr) \
    asm volatile("ldmatrix.sync.aligned.m8n8.x4.shared.b16 {%0,%1,%2,%3}, [%4];" \
                 : "=r"(r0), "=r"(r1), "=r"(r2), "=r"(r3) : "r"(addr))

#define LDMATRIX_X2(r0, r1, addr) \
    asm volatile("ldmatrix.sync.aligned.m8n8.x2.shared.b16 {%0,%1}, [%2];" \
                 : "=r"(r0), "=r"(r1) : "r"(addr))

#define MMA_TF32(d, a, b) \
    asm volatile("mma.sync.aligned.m16n8k8.row.col.f32.tf32.tf32.f32 " \
                 "{%0,%1,%2,%3}, {%4,%5,%6,%7}, {%8,%9}, {%0,%1,%2,%3};" \
                 : "+f"((d)[0]), "+f"((d)[1]), "+f"((d)[2]), "+f"((d)[3]) \
                 : "r"((a)[0]), "r"((a)[1]), "r"((a)[2]), "r"((a)[3]), \
                   "r"((b)[0]), "r"((b)[1]))

// SMEM layout (relative to 1024-aligned base), all in bytes
#define OFF_A0    0
#define OFF_A1    16384
#define OFF_B0    32768
#define OFF_B1    49152
#define OFF_BIAS  65536      // 512 floats
#define SMEM_REQ  (65536 + 2048 + 1024)

// ---------------------------------------------------------------------------
// tf32 mma.sync GEMM: D[m0..m0+127, n0..n0+127] = relu(A @ W^T + bias)
// QKV=true : A = concat(X[.,512], STE[.,1024]) (K=1536), W per blockIdx.z,
//            scatter-epilogue into g_q/g_k/g_v [B,N,K,T,d]
// QKV=false: A = g_attn (K=512), W = Wo, contiguous epilogue into dout
// Tile: BM=128, BN=128, BK=32; 256 thr = 8 warps (2 M x 4 N), warp tile 64x32.
// ---------------------------------------------------------------------------
template<bool QKV>
__global__ __launch_bounds__(256) void gemm_mma(
    const float* __restrict__ X, const float* __restrict__ STE,
    const float* __restrict__ W0, const float* __restrict__ W1, const float* __restrict__ W2,
    const float* __restrict__ b0, const float* __restrict__ b1, const float* __restrict__ b2,
    float* __restrict__ dout)
{
    constexpr int NC   = QKV ? 48 : 16;     // K chunks of 32
    constexpr int KDIM = QKV ? 1536 : 512;

    extern __shared__ char raw[];
    const uint32_t sb_raw = smem_u32(raw);
    const uint32_t sb0 = (sb_raw + 1023u) & ~1023u;
    char* sm = raw + (sb0 - sb_raw);
    float* s_bias = (float*)(sm + OFF_BIAS);

    const int tid  = threadIdx.x;
    const int lane = tid & 31;
    const int wid  = tid >> 5;
    const int wm   = wid & 1;       // 0..1  (M groups of 64)
    const int wn   = wid >> 1;      // 0..3  (N groups of 32)

    const int n0 = blockIdx.x * 128;
    const int m0 = blockIdx.y * 128;
    const int z  = QKV ? blockIdx.z : 0;
    const float* __restrict__ W    = (z == 0) ? W0 : (z == 1) ? W1 : W2;
    const float* __restrict__ bias = (z == 0) ? b0 : (z == 1) ? b1 : b2;

    s_bias[tid]       = bias[tid];
    s_bias[tid + 256] = bias[tid + 256];

    // ldmatrix per-thread address components
    const int a_row = wm * 64 + ((lane >> 3) & 1) * 8 + (lane & 7);
    const int a_kb  = (lane >> 4) * 16;
    const int b_row = wn * 32 + (lane & 7);
    const int b_kb  = ((lane >> 3) & 1) * 16;

    float acc[4][4][4];
    #pragma unroll
    for (int i = 0; i < 4; ++i)
        #pragma unroll
        for (int j = 0; j < 4; ++j)
            #pragma unroll
            for (int c = 0; c < 4; ++c) acc[i][j][c] = 0.f;

    uint32_t ra[4][4], rb[4][4];    // tf32-converted prefetch regs

    // LDG a chunk into regs (convert fp32 -> tf32)
    auto ldg_chunk = [&](int kc) {
        const int col0 = kc * 32;
        #pragma unroll
        for (int it = 0; it < 4; ++it) {
            const int pos = tid + it * 256;
            const int row = pos >> 3, c4 = pos & 7;
            const int gc  = col0 + c4 * 4;
            const float* src;
            if (QKV) src = (gc < 512) ? (X + (size_t)(m0 + row) * 512 + gc)
                                      : (STE + (size_t)(m0 + row) * 1024 + (gc - 512));
            else     src = (const float*)g_attn + (size_t)(m0 + row) * 512 + gc;
            float4 a = *(const float4*)src;
            ra[it][0] = f2tf32(a.x); ra[it][1] = f2tf32(a.y);
            ra[it][2] = f2tf32(a.z); ra[it][3] = f2tf32(a.w);
        }
        #pragma unroll
        for (int it = 0; it < 4; ++it) {
            const int pos = tid + it * 256;
            const int row = pos >> 3, c4 = pos & 7;
            float4 w = *(const float4*)(W + (size_t)(n0 + row) * KDIM + col0 + c4 * 4);
            rb[it][0] = f2tf32(w.x); rb[it][1] = f2tf32(w.y);
            rb[it][2] = f2tf32(w.z); rb[it][3] = f2tf32(w.w);
        }
    };
    auto sts_chunk = [&](int buf) {
        char* ab = sm + (buf ? OFF_A1 : OFF_A0);
        char* bb = sm + (buf ? OFF_B1 : OFF_B0);
        #pragma unroll
        for (int it = 0; it < 4; ++it) {
            const int pos = tid + it * 256;
            const int row = pos >> 3, c4 = pos & 7;
            *(uint4*)(ab + SWZ(row * 128 + c4 * 16)) =
                make_uint4(ra[it][0], ra[it][1], ra[it][2], ra[it][3]);
        }
        #pragma unroll
        for (int it = 0; it < 4; ++it) {
            const int pos = tid + it * 256;
            const int row = pos >> 3, c4 = pos & 7;
            *(uint4*)(bb + SWZ(row * 128 + c4 * 16)) =
                make_uint4(rb[it][0], rb[it][1], rb[it][2], rb[it][3]);
        }
    };
    auto compute = [&](int buf) {
        const uint32_t abase = sb0 + (buf ? OFF_A1 : OFF_A0);
        const uint32_t bbase = sb0 + (buf ? OFF_B1 : OFF_B0);
        #pragma unroll
        for (int ks = 0; ks < 4; ++ks) {
            uint32_t af[4][4], bf[4][2];
            #pragma unroll
            for (int mt = 0; mt < 4; ++mt) {
                const uint32_t addr = abase +
                    SWZ((a_row + mt * 16) * 128 + ks * 32 + a_kb);
                LDMATRIX_X4(af[mt][0], af[mt][1], af[mt][2], af[mt][3], addr);
            }
            #pragma unroll
            for (int nt = 0; nt < 4; ++nt) {
                const uint32_t addr = bbase +
                    SWZ((b_row + nt * 8) * 128 + ks * 32 + b_kb);
                LDMATRIX_X2(bf[nt][0], bf[nt][1], addr);
            }
            #pragma unroll
            for (int mt = 0; mt < 4; ++mt)
                #pragma unroll
                for (int nt = 0; nt < 4; ++nt)
                    MMA_TF32(acc[mt][nt], af[mt], bf[nt]);
        }
    };

    // Pipeline: prologue
    ldg_chunk(0);
    sts_chunk(0);
    __syncthreads();

    #pragma unroll 1
    for (int c = 0; c < NC; ++c) {
        if (c + 1 < NC) ldg_chunk(c + 1);
        compute(c & 1);
        if (c + 1 < NC) sts_chunk((c + 1) & 1);
        __syncthreads();
    }

    // Epilogue: bias + relu + store
    float* gq = g_q; float* gk = g_k; float* gv = g_v;   // device symbols
    #pragma unroll
    for (int mt = 0; mt < 4; ++mt) {
        const int R0 = m0 + wm * 64 + mt * 16 + (lane >> 2);
        const int R1 = R0 + 8;
        #pragma unroll
        for (int nt = 0; nt < 4; ++nt) {
            const int o = n0 + wn * 32 + nt * 8 + (lane & 3) * 2;
            const float bx = s_bias[o], by = s_bias[o + 1];
            float v0 = acc[mt][nt][0] + bx; v0 = v0 > 0.f ? v0 : 0.f;
            float v1 = acc[mt][nt][1] + by; v1 = v1 > 0.f ? v1 : 0.f;
            float v2 = acc[mt][nt][2] + bx; v2 = v2 > 0.f ? v2 : 0.f;
            float v3 = acc[mt][nt][3] + by; v3 = v3 > 0.f ? v3 : 0.f;
            if (QKV) {
                float* outp = (z == 0) ? gq : (z == 1) ? gk : gv;
                const int head = o >> 6, jj = o & 63;
                {
                    const int b_ = R0 >> 13, t_ = (R0 >> 6) & 127, n_ = R0 & 63;
                    const size_t idx = (((size_t)(b_ * NN + n_) * KH + head) * TT + t_) * DH + jj;
                    *(float2*)(outp + idx) = make_float2(v0, v1);
                }
                {
                    const int b_ = R1 >> 13, t_ = (R1 >> 6) & 127, n_ = R1 & 63;
                    const size_t idx = (((size_t)(b_ * NN + n_) * KH + head) * TT + t_) * DH + jj;
                    *(float2*)(outp + idx) = make_float2(v2, v3);
                }
            } else {
                *(float2*)(dout + (size_t)R0 * DD + o) = make_float2(v0, v1);
                *(float2*)(dout + (size_t)R1 * DD + o) = make_float2(v2, v3);
            }
        }
    }
}

// ---------------------------------------------------------------------------
// Attention: one block per (b, n, head); 128 threads, one query row each.
// Writes directly into [B,T,N,D] so the output projection is a plain GEMM.
// ---------------------------------------------------------------------------
__global__ __launch_bounds__(128) void attn_kernel()
{
    extern __shared__ float smf[];
    float* Ks = smf;                 // 128*64
    float* Vs = smf + 8192;          // 128*64
    float* Ss = smf + 16384;         // 128*129 (padded)

    const int head = blockIdx.x;
    const int n    = blockIdx.y;
    const int b    = blockIdx.z;
    const size_t base = ((size_t)(b * NN + n) * KH + head) * (TT * DH);

    const int tid = threadIdx.x;
    const int t   = tid;

    const float4* k4 = (const float4*)(g_k + base);
    const float4* v4 = (const float4*)(g_v + base);
    float4* Ks4 = (float4*)Ks;
    float4* Vs4 = (float4*)Vs;
    #pragma unroll 4
    for (int i = tid; i < (TT * DH) / 4; i += 128) {
        Ks4[i] = k4[i];
        Vs4[i] = v4[i];
    }

    float4 q[16];
    const float4* q4 = (const float4*)(g_q + base + (size_t)t * DH);
    #pragma unroll
    for (int i = 0; i < 16; ++i) q[i] = q4[i];

    __syncthreads();

    float m = -INFINITY;
    for (int s = 0; s <= t; ++s) {
        const float4* kr = (const float4*)(Ks + s * DH);
        float a0 = 0.f, a1 = 0.f, a2 = 0.f, a3 = 0.f;
        #pragma unroll
        for (int i = 0; i < 16; ++i) {
            float4 kv = kr[i];
            a0 += q[i].x * kv.x;
            a1 += q[i].y * kv.y;
            a2 += q[i].z * kv.z;
            a3 += q[i].w * kv.w;
        }
        const float sc = (a0 + a1 + a2 + a3) * 0.125f;
        Ss[t * 129 + s] = sc;
        m = fmaxf(m, sc);
    }

    float l = 0.f;
    for (int s = 0; s <= t; ++s) {
        const float p = __expf(Ss[t * 129 + s] - m);
        Ss[t * 129 + s] = p;
        l += p;
    }
    const float inv = 1.f / l;

    const size_t row_off = ((size_t)(b * TT + t) * NN + n) * DD + head * DH;
    #pragma unroll
    for (int j0 = 0; j0 < DH; j0 += 32) {
        float acc[32];
        #pragma unroll
        for (int c = 0; c < 32; ++c) acc[c] = 0.f;
        for (int s = 0; s <= t; ++s) {
            const float p = Ss[t * 129 + s];
            const float4* vr = (const float4*)(Vs + s * DH + j0);
            #pragma unroll
            for (int c = 0; c < 8; ++c) {
                float4 vv = vr[c];
                acc[c*4+0] += p * vv.x;
                acc[c*4+1] += p * vv.y;
                acc[c*4+2] += p * vv.z;
                acc[c*4+3] += p * vv.w;
            }
        }
        #pragma unroll
        for (int c = 0; c < 8; ++c) {
            float4 r = make_float4(acc[c*4+0]*inv, acc[c*4+1]*inv, acc[c*4+2]*inv, acc[c*4+3]*inv);
            *(float4*)(g_attn + row_off + j0 + c * 4) = r;
        }
    }
}

// ---------------------------------------------------------------------------
extern "C" void kernel_launch(void* const* d_in, const int* in_sizes, int n_in,
                              void* d_out, int out_size)
{
    const float* X   = (const float*)d_in[0];
    const float* STE = (const float*)d_in[1];
    const float* Wq  = (const float*)d_in[2];
    const float* bq  = (const float*)d_in[3];
    const float* Wk  = (const float*)d_in[4];
    const float* bk  = (const float*)d_in[5];
    const float* Wv  = (const float*)d_in[6];
    const float* bv  = (const float*)d_in[7];
    const float* Wo  = (const float*)d_in[8];
    const float* bo  = (const float*)d_in[9];
    float* out = (float*)d_out;

    cudaFuncSetAttribute(gemm_mma<true>,  cudaFuncAttributeMaxDynamicSharedMemorySize, SMEM_REQ);
    cudaFuncSetAttribute(gemm_mma<false>, cudaFuncAttributeMaxDynamicSharedMemorySize, SMEM_REQ);

    // QKV: (Ntiles=4, Mtiles=512, qkv=3)
    gemm_mma<true><<<dim3(4, 512, 3), 256, SMEM_REQ>>>(X, STE, Wq, Wk, Wv, bq, bk, bv, nullptr);

    // Attention: 4096 blocks (head, n, b)
    const int attn_smem = (16384 + 128 * 129) * (int)sizeof(float);
    cudaFuncSetAttribute(attn_kernel, cudaFuncAttributeMaxDynamicSharedMemorySize, attn_smem);
    attn_kernel<<<dim3(KH, NN, BB), 128, attn_smem>>>();

    // Output projection (A = g_attn read inside the kernel)
    gemm_mma<false><<<dim3(4, 512, 1), 256, SMEM_REQ>>>(nullptr, nullptr, Wo, nullptr, nullptr,
                                                        bo, nullptr, nullptr, out);
}

// round 4
// speedup vs baseline: 3.1561x; 1.2267x over previous
#include <cuda_runtime.h>
#include <math.h>
#include <stdint.h>

// Problem dims
#define BB   8
#define TT   128
#define NN   64
#define KH   8
#define DH   64
#define DD   512
#define MTOT 65536

// Scratch (device globals — allocation-free rule)
__device__ uint32_t g_h[(size_t)MTOT*1536];       // tf32 concat(X,STE)
__device__ uint32_t g_w[(size_t)3*512*1536];      // tf32 Wq|Wk|Wv
__device__ uint32_t g_wo[(size_t)512*512];        // tf32 Wo
__device__ float g_q[(size_t)BB*NN*KH*TT*DH];     // [B,N,K,T,d]
__device__ float g_k[(size_t)BB*NN*KH*TT*DH];
__device__ float g_v[(size_t)BB*NN*KH*TT*DH];
__device__ float g_attn[(size_t)MTOT*DD];         // [B,T,N,D], tf32-rounded values

// ---------------------------------------------------------------------------
// Helpers
// ---------------------------------------------------------------------------
__device__ __forceinline__ uint32_t smem_u32(const void* p) {
    uint32_t a;
    asm("{ .reg .u64 t; cvta.to.shared.u64 t, %1; cvt.u32.u64 %0, t; }" : "=r"(a) : "l"(p));
    return a;
}
__device__ __forceinline__ uint32_t f2tf32(float x) {
    uint32_t u;
    asm("cvt.rna.tf32.f32 %0, %1;" : "=r"(u) : "f"(x));
    return u;
}
__device__ __forceinline__ float tf32round(float x) {
    return __uint_as_float(f2tf32(x));
}

#define CP_ASYNC16(dst, src) \
    asm volatile("cp.async.cg.shared.global [%0], [%1], 16;" :: "r"(dst), "l"(src))
#define CP_COMMIT()  asm volatile("cp.async.commit_group;" ::: "memory")
#define CP_WAIT1()   asm volatile("cp.async.wait_group 1;" ::: "memory")

#define LDMATRIX_X4(r0, r1, r2, r3, addr) \
    asm volatile("ldmatrix.sync.aligned.m8n8.x4.shared.b16 {%0,%1,%2,%3}, [%4];" \
                 : "=r"(r0), "=r"(r1), "=r"(r2), "=r"(r3) : "r"(addr))

#define MMA_TF32(d, a, b) \
    asm volatile("mma.sync.aligned.m16n8k8.row.col.f32.tf32.tf32.f32 " \
                 "{%0,%1,%2,%3}, {%4,%5,%6,%7}, {%8,%9}, {%0,%1,%2,%3};" \
                 : "+f"((d)[0]), "+f"((d)[1]), "+f"((d)[2]), "+f"((d)[3]) \
                 : "r"((a)[0]), "r"((a)[1]), "r"((a)[2]), "r"((a)[3]), \
                   "r"((b)[0]), "r"((b)[1]))

// SMEM: 3 stages x (A 16KB + B 16KB) = 98304 B, bias 2048 B, +1024 align slack
#define STAGE_BYTES 32768
#define OFF_BIAS    98304
#define SMEM_REQ    (98304 + 2048 + 1024)

// ---------------------------------------------------------------------------
// Prepass: tf32 conversions
// ---------------------------------------------------------------------------
__global__ __launch_bounds__(384) void prep_h(const float* __restrict__ X,
                                              const float* __restrict__ STE)
{
    const int row = blockIdx.x;           // 0..65535
    const int c   = threadIdx.x * 4;      // 0..1532
    float4 v;
    if (c < 512) v = *(const float4*)(X + (size_t)row * 512 + c);
    else         v = *(const float4*)(STE + (size_t)row * 1024 + (c - 512));
    uint4 u = make_uint4(f2tf32(v.x), f2tf32(v.y), f2tf32(v.z), f2tf32(v.w));
    *(uint4*)(g_h + (size_t)row * 1536 + c) = u;
}

__global__ __launch_bounds__(384) void prep_w(const float* __restrict__ Wq,
                                              const float* __restrict__ Wk,
                                              const float* __restrict__ Wv,
                                              const float* __restrict__ Wo)
{
    const int b = blockIdx.x;
    if (b < 1536) {                        // Wq/Wk/Wv rows
        const int z = b >> 9, n = b & 511;
        const float* W = (z == 0) ? Wq : (z == 1) ? Wk : Wv;
        const int c = threadIdx.x * 4;
        float4 v = *(const float4*)(W + (size_t)n * 1536 + c);
        *(uint4*)(g_w + (size_t)b * 1536 + c) =
            make_uint4(f2tf32(v.x), f2tf32(v.y), f2tf32(v.z), f2tf32(v.w));
    } else {                               // Wo rows (512 rows x 512 cols)
        const int n = b - 1536;
        if (threadIdx.x < 128) {
            const int c = threadIdx.x * 4;
            float4 v = *(const float4*)(Wo + (size_t)n * 512 + c);
            *(uint4*)(g_wo + (size_t)n * 512 + c) =
                make_uint4(f2tf32(v.x), f2tf32(v.y), f2tf32(v.z), f2tf32(v.w));
        }
    }
}

// ---------------------------------------------------------------------------
// tf32 mma.sync GEMM, cp.async 3-stage. CTA 128x128x32, 4 warps (2Mx2N),
// warp tile 64x64. Operands pre-converted to tf32 (g_h/g_w/g_wo/g_attn).
// QKV=true : A=g_h (K=1536), W=g_w[z], scatter epilogue into g_q/g_k/g_v
// QKV=false: A=g_attn (K=512), W=g_wo, contiguous epilogue into dout
// ---------------------------------------------------------------------------
template<bool QKV>
__global__ __launch_bounds__(128, 2) void gemm2(
    const float* __restrict__ bias0, const float* __restrict__ bias1,
    const float* __restrict__ bias2, float* __restrict__ dout)
{
    constexpr int KDIM = QKV ? 1536 : 512;
    constexpr int NC   = KDIM / 32;

    extern __shared__ char raw[];
    const uint32_t sb_raw = smem_u32(raw);
    const uint32_t sb0 = (sb_raw + 1023u) & ~1023u;
    char* sm = raw + (sb0 - sb_raw);
    float* s_bias = (float*)(sm + OFF_BIAS);

    const int tid  = threadIdx.x;
    const int lane = tid & 31;
    const int wid  = tid >> 5;
    const int wm   = wid & 1;
    const int wn   = wid >> 1;

    const int n0 = blockIdx.x * 128;
    const int m0 = blockIdx.y * 128;
    const int z  = QKV ? blockIdx.z : 0;

    const uint32_t* __restrict__ A = QKV ? g_h : (const uint32_t*)g_attn;
    const uint32_t* __restrict__ W = QKV ? (g_w + (size_t)z * 512 * 1536) : g_wo;
    const float* __restrict__ bias = (z == 0) ? bias0 : (z == 1) ? bias1 : bias2;

    ((float4*)s_bias)[tid] = ((const float4*)bias)[tid];   // 512 floats

    // cp.async issue for one K-chunk into a stage
    auto issue = [&](int kc, int stage) {
        const uint32_t as = sb0 + stage * STAGE_BYTES;
        const uint32_t bs = as + 16384;
        const uint32_t* Ap = A + (size_t)m0 * KDIM + kc * 32;
        const uint32_t* Wp = W + (size_t)n0 * KDIM + kc * 32;
        #pragma unroll
        for (int it = 0; it < 8; ++it) {
            const int pos = tid + it * 128;
            const int row = pos >> 3, c4 = pos & 7;
            const uint32_t d = as + row * 128 + ((c4 * 16) ^ ((row & 7) * 16));
            CP_ASYNC16(d, Ap + (size_t)row * KDIM + c4 * 4);
        }
        #pragma unroll
        for (int it = 0; it < 8; ++it) {
            const int pos = tid + it * 128;
            const int row = pos >> 3, c4 = pos & 7;
            const uint32_t d = bs + row * 128 + ((c4 * 16) ^ ((row & 7) * 16));
            CP_ASYNC16(d, Wp + (size_t)row * KDIM + c4 * 4);
        }
    };

    float acc[4][8][4];
    #pragma unroll
    for (int i = 0; i < 4; ++i)
        #pragma unroll
        for (int j = 0; j < 8; ++j)
            #pragma unroll
            for (int c = 0; c < 4; ++c) acc[i][j][c] = 0.f;

    // ldmatrix per-thread address components
    const int a_row = wm * 64 + ((lane >> 3) & 1) * 8 + (lane & 7);
    const int a_kb  = (lane >> 4) * 16;
    const int xa    = (a_row & 7) * 16;
    const int b_row = wn * 64 + ((lane >> 4) & 1) * 8 + (lane & 7);
    const int b_kb  = ((lane >> 3) & 1) * 16;
    const int xb    = (b_row & 7) * 16;

    auto compute = [&](int buf) {
        const uint32_t abase = sb0 + buf * STAGE_BYTES;
        const uint32_t bbase = abase + 16384;
        #pragma unroll
        for (int ks = 0; ks < 4; ++ks) {
            uint32_t af[4][4], bf[8][2];
            #pragma unroll
            for (int mt = 0; mt < 4; ++mt) {
                const uint32_t addr = abase + (a_row + mt * 16) * 128
                                    + ((ks * 32 + a_kb) ^ xa);
                LDMATRIX_X4(af[mt][0], af[mt][1], af[mt][2], af[mt][3], addr);
            }
            #pragma unroll
            for (int np = 0; np < 4; ++np) {
                const uint32_t addr = bbase + (b_row + np * 16) * 128
                                    + ((ks * 32 + b_kb) ^ xb);
                LDMATRIX_X4(bf[2*np][0], bf[2*np][1], bf[2*np+1][0], bf[2*np+1][1], addr);
            }
            #pragma unroll
            for (int mt = 0; mt < 4; ++mt)
                #pragma unroll
                for (int nt = 0; nt < 8; ++nt)
                    MMA_TF32(acc[mt][nt], af[mt], bf[nt]);
        }
    };

    // Prologue: 2 stages in flight
    issue(0, 0); CP_COMMIT();
    issue(1, 1); CP_COMMIT();

    #pragma unroll 1
    for (int c = 0; c < NC; ++c) {
        CP_WAIT1();
        __syncthreads();
        if (c + 2 < NC) issue(c + 2, (c + 2) % 3);
        CP_COMMIT();
        compute(c % 3);
    }

    // Epilogue: bias + relu + store
    float* gq = g_q; float* gk = g_k; float* gv = g_v;
    #pragma unroll
    for (int mt = 0; mt < 4; ++mt) {
        const int R0 = m0 + wm * 64 + mt * 16 + (lane >> 2);
        const int R1 = R0 + 8;
        #pragma unroll
        for (int nt = 0; nt < 8; ++nt) {
            const int o = n0 + wn * 64 + nt * 8 + (lane & 3) * 2;
            const float bx = s_bias[o], by = s_bias[o + 1];
            float v0 = acc[mt][nt][0] + bx; v0 = v0 > 0.f ? v0 : 0.f;
            float v1 = acc[mt][nt][1] + by; v1 = v1 > 0.f ? v1 : 0.f;
            float v2 = acc[mt][nt][2] + bx; v2 = v2 > 0.f ? v2 : 0.f;
            float v3 = acc[mt][nt][3] + by; v3 = v3 > 0.f ? v3 : 0.f;
            if (QKV) {
                float* outp = (z == 0) ? gq : (z == 1) ? gk : gv;
                const int head = o >> 6, jj = o & 63;
                {
                    const int b_ = R0 >> 13, t_ = (R0 >> 6) & 127, n_ = R0 & 63;
                    const size_t idx = (((size_t)(b_ * NN + n_) * KH + head) * TT + t_) * DH + jj;
                    *(float2*)(outp + idx) = make_float2(v0, v1);
                }
                {
                    const int b_ = R1 >> 13, t_ = (R1 >> 6) & 127, n_ = R1 & 63;
                    const size_t idx = (((size_t)(b_ * NN + n_) * KH + head) * TT + t_) * DH + jj;
                    *(float2*)(outp + idx) = make_float2(v2, v3);
                }
            } else {
                *(float2*)(dout + (size_t)R0 * DD + o) = make_float2(v0, v1);
                *(float2*)(dout + (size_t)R1 * DD + o) = make_float2(v2, v3);
            }
        }
    }
}

// ---------------------------------------------------------------------------
// Attention: one block per (b, n, head); 128 threads, one query row each.
// Output pre-rounded to tf32 so the proj GEMM consumes it without cvt.
// ---------------------------------------------------------------------------
__global__ __launch_bounds__(128) void attn_kernel()
{
    extern __shared__ float smf[];
    float* Ks = smf;                 // 128*64
    float* Vs = smf + 8192;          // 128*64
    float* Ss = smf + 16384;         // 128*129 (padded)

    const int head = blockIdx.x;
    const int n    = blockIdx.y;
    const int b    = blockIdx.z;
    const size_t base = ((size_t)(b * NN + n) * KH + head) * (TT * DH);

    const int tid = threadIdx.x;
    const int t   = tid;

    const float4* k4 = (const float4*)(g_k + base);
    const float4* v4 = (const float4*)(g_v + base);
    float4* Ks4 = (float4*)Ks;
    float4* Vs4 = (float4*)Vs;
    #pragma unroll 4
    for (int i = tid; i < (TT * DH) / 4; i += 128) {
        Ks4[i] = k4[i];
        Vs4[i] = v4[i];
    }

    float4 q[16];
    const float4* q4 = (const float4*)(g_q + base + (size_t)t * DH);
    #pragma unroll
    for (int i = 0; i < 16; ++i) q[i] = q4[i];

    __syncthreads();

    float m = -INFINITY;
    for (int s = 0; s <= t; ++s) {
        const float4* kr = (const float4*)(Ks + s * DH);
        float a0 = 0.f, a1 = 0.f, a2 = 0.f, a3 = 0.f;
        #pragma unroll
        for (int i = 0; i < 16; ++i) {
            float4 kv = kr[i];
            a0 += q[i].x * kv.x;
            a1 += q[i].y * kv.y;
            a2 += q[i].z * kv.z;
            a3 += q[i].w * kv.w;
        }
        const float sc = (a0 + a1 + a2 + a3) * 0.125f;
        Ss[t * 129 + s] = sc;
        m = fmaxf(m, sc);
    }

    float l = 0.f;
    for (int s = 0; s <= t; ++s) {
        const float p = __expf(Ss[t * 129 + s] - m);
        Ss[t * 129 + s] = p;
        l += p;
    }
    const float inv = 1.f / l;

    const size_t row_off = ((size_t)(b * TT + t) * NN + n) * DD + head * DH;
    #pragma unroll
    for (int j0 = 0; j0 < DH; j0 += 32) {
        float acc[32];
        #pragma unroll
        for (int c = 0; c < 32; ++c) acc[c] = 0.f;
        for (int s = 0; s <= t; ++s) {
            const float p = Ss[t * 129 + s];
            const float4* vr = (const float4*)(Vs + s * DH + j0);
            #pragma unroll
            for (int c = 0; c < 8; ++c) {
                float4 vv = vr[c];
                acc[c*4+0] += p * vv.x;
                acc[c*4+1] += p * vv.y;
                acc[c*4+2] += p * vv.z;
                acc[c*4+3] += p * vv.w;
            }
        }
        #pragma unroll
        for (int c = 0; c < 8; ++c) {
            float4 r = make_float4(tf32round(acc[c*4+0]*inv), tf32round(acc[c*4+1]*inv),
                                   tf32round(acc[c*4+2]*inv), tf32round(acc[c*4+3]*inv));
            *(float4*)(g_attn + row_off + j0 + c * 4) = r;
        }
    }
}

// ---------------------------------------------------------------------------
extern "C" void kernel_launch(void* const* d_in, const int* in_sizes, int n_in,
                              void* d_out, int out_size)
{
    const float* X   = (const float*)d_in[0];
    const float* STE = (const float*)d_in[1];
    const float* Wq  = (const float*)d_in[2];
    const float* bq  = (const float*)d_in[3];
    const float* Wk  = (const float*)d_in[4];
    const float* bk  = (const float*)d_in[5];
    const float* Wv  = (const float*)d_in[6];
    const float* bv  = (const float*)d_in[7];
    const float* Wo  = (const float*)d_in[8];
    const float* bo  = (const float*)d_in[9];
    float* out = (float*)d_out;

    // Prepass: tf32 copies
    prep_h<<<MTOT, 384>>>(X, STE);
    prep_w<<<1536 + 512, 384>>>(Wq, Wk, Wv, Wo);

    cudaFuncSetAttribute(gemm2<true>,  cudaFuncAttributeMaxDynamicSharedMemorySize, SMEM_REQ);
    cudaFuncSetAttribute(gemm2<false>, cudaFuncAttributeMaxDynamicSharedMemorySize, SMEM_REQ);

    // QKV: (4 n-tiles, 512 m-tiles, 3 weights)
    gemm2<true><<<dim3(4, 512, 3), 128, SMEM_REQ>>>(bq, bk, bv, nullptr);

    // Attention
    const int attn_smem = (16384 + 128 * 129) * (int)sizeof(float);
    cudaFuncSetAttribute(attn_kernel, cudaFuncAttributeMaxDynamicSharedMemorySize, attn_smem);
    attn_kernel<<<dim3(KH, NN, BB), 128, attn_smem>>>();

    // Output projection
    gemm2<false><<<dim3(4, 512, 1), 128, SMEM_REQ>>>(bo, bo, bo, out);
}

// round 5
// speedup vs baseline: 4.2925x; 1.3600x over previous
#include <cuda_runtime.h>
#include <math.h>
#include <stdint.h>

// Problem dims
#define BB   8
#define TT   128
#define NN   64
#define KH   8
#define DH   64
#define DD   512
#define MTOT 65536

// Scratch (device globals — allocation-free rule)
__device__ uint32_t g_h[(size_t)MTOT*1536];       // tf32 concat(X,STE)
__device__ uint32_t g_w[(size_t)3*512*1536];      // tf32 Wq|Wk|Wv
__device__ uint32_t g_wo[(size_t)512*512];        // tf32 Wo
__device__ float g_q[(size_t)BB*NN*KH*TT*DH];     // [B,N,K,T,d], tf32-rounded
__device__ float g_k[(size_t)BB*NN*KH*TT*DH];
__device__ float g_v[(size_t)BB*NN*KH*TT*DH];
__device__ float g_attn[(size_t)MTOT*DD];         // [B,T,N,D], tf32-rounded

// ---------------------------------------------------------------------------
// Helpers
// ---------------------------------------------------------------------------
__device__ __forceinline__ uint32_t smem_u32(const void* p) {
    uint32_t a;
    asm("{ .reg .u64 t; cvta.to.shared.u64 t, %1; cvt.u32.u64 %0, t; }" : "=r"(a) : "l"(p));
    return a;
}
__device__ __forceinline__ uint32_t f2tf32(float x) {
    uint32_t u;
    asm("cvt.rna.tf32.f32 %0, %1;" : "=r"(u) : "f"(x));
    return u;
}
__device__ __forceinline__ float tf32round(float x) {
    return __uint_as_float(f2tf32(x));
}

#define CP_ASYNC16(dst, src) \
    asm volatile("cp.async.cg.shared.global [%0], [%1], 16;" :: "r"(dst), "l"(src))
#define CP_COMMIT()  asm volatile("cp.async.commit_group;" ::: "memory")
#define CP_WAIT1()   asm volatile("cp.async.wait_group 1;" ::: "memory")

#define LDMATRIX_X4(r0, r1, r2, r3, addr) \
    asm volatile("ldmatrix.sync.aligned.m8n8.x4.shared.b16 {%0,%1,%2,%3}, [%4];" \
                 : "=r"(r0), "=r"(r1), "=r"(r2), "=r"(r3) : "r"(addr))

#define MMA_TF32(d, a, b) \
    asm volatile("mma.sync.aligned.m16n8k8.row.col.f32.tf32.tf32.f32 " \
                 "{%0,%1,%2,%3}, {%4,%5,%6,%7}, {%8,%9}, {%0,%1,%2,%3};" \
                 : "+f"((d)[0]), "+f"((d)[1]), "+f"((d)[2]), "+f"((d)[3]) \
                 : "r"((a)[0]), "r"((a)[1]), "r"((a)[2]), "r"((a)[3]), \
                   "r"((b)[0]), "r"((b)[1]))

// GEMM SMEM: 3 stages x (A 16KB + B 16KB), bias 2048 B, +1024 align slack
#define STAGE_BYTES 32768
#define OFF_BIAS    98304
#define SMEM_REQ    (98304 + 2048 + 1024)

// Attention SMEM (bytes): Q/K padded stride 272 B (68 w), Vt/P stride 528 B (132 w)
#define AT_Q      0
#define AT_K      34816
#define AT_V      69632           // 64 rows x 528
#define AT_SMEM   103424
#define QK_STRIDE 272
#define VP_STRIDE 528

// ---------------------------------------------------------------------------
// Prepass: tf32 conversions
// ---------------------------------------------------------------------------
__global__ __launch_bounds__(384) void prep_h(const float* __restrict__ X,
                                              const float* __restrict__ STE)
{
    const int row = blockIdx.x;
    const int c   = threadIdx.x * 4;
    float4 v;
    if (c < 512) v = *(const float4*)(X + (size_t)row * 512 + c);
    else         v = *(const float4*)(STE + (size_t)row * 1024 + (c - 512));
    *(uint4*)(g_h + (size_t)row * 1536 + c) =
        make_uint4(f2tf32(v.x), f2tf32(v.y), f2tf32(v.z), f2tf32(v.w));
}

__global__ __launch_bounds__(384) void prep_w(const float* __restrict__ Wq,
                                              const float* __restrict__ Wk,
                                              const float* __restrict__ Wv,
                                              const float* __restrict__ Wo)
{
    const int b = blockIdx.x;
    if (b < 1536) {
        const int z = b >> 9, n = b & 511;
        const float* W = (z == 0) ? Wq : (z == 1) ? Wk : Wv;
        const int c = threadIdx.x * 4;
        float4 v = *(const float4*)(W + (size_t)n * 1536 + c);
        *(uint4*)(g_w + (size_t)b * 1536 + c) =
            make_uint4(f2tf32(v.x), f2tf32(v.y), f2tf32(v.z), f2tf32(v.w));
    } else {
        const int n = b - 1536;
        if (threadIdx.x < 128) {
            const int c = threadIdx.x * 4;
            float4 v = *(const float4*)(Wo + (size_t)n * 512 + c);
            *(uint4*)(g_wo + (size_t)n * 512 + c) =
                make_uint4(f2tf32(v.x), f2tf32(v.y), f2tf32(v.z), f2tf32(v.w));
        }
    }
}

// ---------------------------------------------------------------------------
// tf32 mma.sync GEMM, cp.async 3-stage. CTA 128x128x32, 4 warps, warp 64x64.
// ---------------------------------------------------------------------------
template<bool QKV>
__global__ __launch_bounds__(128, 2) void gemm2(
    const float* __restrict__ bias0, const float* __restrict__ bias1,
    const float* __restrict__ bias2, float* __restrict__ dout)
{
    constexpr int KDIM = QKV ? 1536 : 512;
    constexpr int NC   = KDIM / 32;

    extern __shared__ char raw[];
    const uint32_t sb_raw = smem_u32(raw);
    const uint32_t sb0 = (sb_raw + 1023u) & ~1023u;
    char* sm = raw + (sb0 - sb_raw);
    float* s_bias = (float*)(sm + OFF_BIAS);

    const int tid  = threadIdx.x;
    const int lane = tid & 31;
    const int wid  = tid >> 5;
    const int wm   = wid & 1;
    const int wn   = wid >> 1;

    const int n0 = blockIdx.x * 128;
    const int m0 = blockIdx.y * 128;
    const int z  = QKV ? blockIdx.z : 0;

    const uint32_t* __restrict__ A = QKV ? g_h : (const uint32_t*)g_attn;
    const uint32_t* __restrict__ W = QKV ? (g_w + (size_t)z * 512 * 1536) : g_wo;
    const float* __restrict__ bias = (z == 0) ? bias0 : (z == 1) ? bias1 : bias2;

    ((float4*)s_bias)[tid] = ((const float4*)bias)[tid];

    auto issue = [&](int kc, int stage) {
        const uint32_t as = sb0 + stage * STAGE_BYTES;
        const uint32_t bs = as + 16384;
        const uint32_t* Ap = A + (size_t)m0 * KDIM + kc * 32;
        const uint32_t* Wp = W + (size_t)n0 * KDIM + kc * 32;
        #pragma unroll
        for (int it = 0; it < 8; ++it) {
            const int pos = tid + it * 128;
            const int row = pos >> 3, c4 = pos & 7;
            const uint32_t d = as + row * 128 + ((c4 * 16) ^ ((row & 7) * 16));
            CP_ASYNC16(d, Ap + (size_t)row * KDIM + c4 * 4);
        }
        #pragma unroll
        for (int it = 0; it < 8; ++it) {
            const int pos = tid + it * 128;
            const int row = pos >> 3, c4 = pos & 7;
            const uint32_t d = bs + row * 128 + ((c4 * 16) ^ ((row & 7) * 16));
            CP_ASYNC16(d, Wp + (size_t)row * KDIM + c4 * 4);
        }
    };

    float acc[4][8][4];
    #pragma unroll
    for (int i = 0; i < 4; ++i)
        #pragma unroll
        for (int j = 0; j < 8; ++j)
            #pragma unroll
            for (int c = 0; c < 4; ++c) acc[i][j][c] = 0.f;

    const int a_row = wm * 64 + ((lane >> 3) & 1) * 8 + (lane & 7);
    const int a_kb  = (lane >> 4) * 16;
    const int xa    = (a_row & 7) * 16;
    const int b_row = wn * 64 + ((lane >> 4) & 1) * 8 + (lane & 7);
    const int b_kb  = ((lane >> 3) & 1) * 16;
    const int xb    = (b_row & 7) * 16;

    auto compute = [&](int buf) {
        const uint32_t abase = sb0 + buf * STAGE_BYTES;
        const uint32_t bbase = abase + 16384;
        #pragma unroll
        for (int ks = 0; ks < 4; ++ks) {
            uint32_t af[4][4], bf[8][2];
            #pragma unroll
            for (int mt = 0; mt < 4; ++mt) {
                const uint32_t addr = abase + (a_row + mt * 16) * 128
                                    + ((ks * 32 + a_kb) ^ xa);
                LDMATRIX_X4(af[mt][0], af[mt][1], af[mt][2], af[mt][3], addr);
            }
            #pragma unroll
            for (int np = 0; np < 4; ++np) {
                const uint32_t addr = bbase + (b_row + np * 16) * 128
                                    + ((ks * 32 + b_kb) ^ xb);
                LDMATRIX_X4(bf[2*np][0], bf[2*np][1], bf[2*np+1][0], bf[2*np+1][1], addr);
            }
            #pragma unroll
            for (int mt = 0; mt < 4; ++mt)
                #pragma unroll
                for (int nt = 0; nt < 8; ++nt)
                    MMA_TF32(acc[mt][nt], af[mt], bf[nt]);
        }
    };

    issue(0, 0); CP_COMMIT();
    issue(1, 1); CP_COMMIT();

    #pragma unroll 1
    for (int c = 0; c < NC; ++c) {
        CP_WAIT1();
        __syncthreads();
        if (c + 2 < NC) issue(c + 2, (c + 2) % 3);
        CP_COMMIT();
        compute(c % 3);
    }

    float* gq = g_q; float* gk = g_k; float* gv = g_v;
    #pragma unroll
    for (int mt = 0; mt < 4; ++mt) {
        const int R0 = m0 + wm * 64 + mt * 16 + (lane >> 2);
        const int R1 = R0 + 8;
        #pragma unroll
        for (int nt = 0; nt < 8; ++nt) {
            const int o = n0 + wn * 64 + nt * 8 + (lane & 3) * 2;
            const float bx = s_bias[o], by = s_bias[o + 1];
            float v0 = acc[mt][nt][0] + bx; v0 = v0 > 0.f ? v0 : 0.f;
            float v1 = acc[mt][nt][1] + by; v1 = v1 > 0.f ? v1 : 0.f;
            float v2 = acc[mt][nt][2] + bx; v2 = v2 > 0.f ? v2 : 0.f;
            float v3 = acc[mt][nt][3] + by; v3 = v3 > 0.f ? v3 : 0.f;
            if (QKV) {
                // round to tf32 so the attention MMA consumes raw bits
                v0 = tf32round(v0); v1 = tf32round(v1);
                v2 = tf32round(v2); v3 = tf32round(v3);
                float* outp = (z == 0) ? gq : (z == 1) ? gk : gv;
                const int head = o >> 6, jj = o & 63;
                {
                    const int b_ = R0 >> 13, t_ = (R0 >> 6) & 127, n_ = R0 & 63;
                    const size_t idx = (((size_t)(b_ * NN + n_) * KH + head) * TT + t_) * DH + jj;
                    *(float2*)(outp + idx) = make_float2(v0, v1);
                }
                {
                    const int b_ = R1 >> 13, t_ = (R1 >> 6) & 127, n_ = R1 & 63;
                    const size_t idx = (((size_t)(b_ * NN + n_) * KH + head) * TT + t_) * DH + jj;
                    *(float2*)(outp + idx) = make_float2(v2, v3);
                }
            } else {
                *(float2*)(dout + (size_t)R0 * DD + o) = make_float2(v0, v1);
                *(float2*)(dout + (size_t)R1 * DD + o) = make_float2(v2, v3);
            }
        }
    }
}

// ---------------------------------------------------------------------------
// Tensor-core attention: one CTA per (b,n,head), 256 thr = 8 warps.
// S = QK^T via mma (warp w owns rows 16w..16w+15), softmax in regs,
// P -> smem (overlays Q/K), O = P@V via mma, write [B,T,N,D] tf32-rounded.
// ---------------------------------------------------------------------------
__global__ __launch_bounds__(256, 2) void attn_tc()
{
    extern __shared__ char smf[];
    const uint32_t sb = smem_u32(smf);

    const int head = blockIdx.x;
    const int n    = blockIdx.y;
    const int b    = blockIdx.z;
    const size_t base = ((size_t)(b * NN + n) * KH + head) * (TT * DH);

    const int tid  = threadIdx.x;
    const int lane = tid & 31;
    const int w    = tid >> 5;

    // ---- load Q, K (row t, stride 272 B) and V transposed (row d, stride 528 B)
    {
        const float4* q4 = (const float4*)(g_q + base);
        const float4* k4 = (const float4*)(g_k + base);
        #pragma unroll
        for (int it = 0; it < 8; ++it) {
            const int pos = tid + it * 256;
            const int t = pos >> 4, d4 = pos & 15;
            *(float4*)(smf + AT_Q + t * QK_STRIDE + d4 * 16) = q4[pos];
            *(float4*)(smf + AT_K + t * QK_STRIDE + d4 * 16) = k4[pos];
        }
        #pragma unroll
        for (int it = 0; it < 8; ++it) {
            const int pos = tid + it * 256;
            const int s = pos & 127, d4 = pos >> 7;
            float4 v = *(const float4*)(g_v + base + (size_t)s * DH + d4 * 4);
            float* vt = (float*)(smf + AT_V) + s;
            vt[(d4 * 4 + 0) * 132] = v.x;
            vt[(d4 * 4 + 1) * 132] = v.y;
            vt[(d4 * 4 + 2) * 132] = v.z;
            vt[(d4 * 4 + 3) * 132] = v.w;
        }
    }
    __syncthreads();

    // ---- S = Q K^T (warp w: rows 16w..16w+15, all 128 cols)
    const int arow = w * 16 + ((lane >> 3) & 1) * 8 + (lane & 7);
    const int akb  = (lane >> 4) * 16;
    const int brow = ((lane >> 4) & 1) * 8 + (lane & 7);
    const int bkb  = ((lane >> 3) & 1) * 16;

    float acc[16][4];
    #pragma unroll
    for (int i = 0; i < 16; ++i)
        #pragma unroll
        for (int c = 0; c < 4; ++c) acc[i][c] = 0.f;

    #pragma unroll
    for (int ks = 0; ks < 8; ++ks) {
        uint32_t af[4];
        LDMATRIX_X4(af[0], af[1], af[2], af[3],
                    sb + AT_Q + arow * QK_STRIDE + ks * 32 + akb);
        #pragma unroll
        for (int np = 0; np < 8; ++np) {
            uint32_t bf[4];
            LDMATRIX_X4(bf[0], bf[1], bf[2], bf[3],
                        sb + AT_K + (brow + np * 16) * QK_STRIDE + ks * 32 + bkb);
            MMA_TF32(acc[2*np],   af, (bf));
            MMA_TF32(acc[2*np+1], af, (bf + 2));
        }
    }

    // ---- softmax (rows r0, r0+8)
    const int r0 = w * 16 + (lane >> 2);
    float mx0 = -1e30f, mx1 = -1e30f;
    #pragma unroll
    for (int nt = 0; nt < 16; ++nt) {
        const int c0 = nt * 8 + (lane & 3) * 2;
        acc[nt][0] = (c0     <= r0    ) ? acc[nt][0] * 0.125f : -1e30f;
        acc[nt][1] = (c0 + 1 <= r0    ) ? acc[nt][1] * 0.125f : -1e30f;
        acc[nt][2] = (c0     <= r0 + 8) ? acc[nt][2] * 0.125f : -1e30f;
        acc[nt][3] = (c0 + 1 <= r0 + 8) ? acc[nt][3] * 0.125f : -1e30f;
        mx0 = fmaxf(mx0, fmaxf(acc[nt][0], acc[nt][1]));
        mx1 = fmaxf(mx1, fmaxf(acc[nt][2], acc[nt][3]));
    }
    mx0 = fmaxf(mx0, __shfl_xor_sync(0xffffffffu, mx0, 1));
    mx0 = fmaxf(mx0, __shfl_xor_sync(0xffffffffu, mx0, 2));
    mx1 = fmaxf(mx1, __shfl_xor_sync(0xffffffffu, mx1, 1));
    mx1 = fmaxf(mx1, __shfl_xor_sync(0xffffffffu, mx1, 2));

    float l0 = 0.f, l1 = 0.f;
    #pragma unroll
    for (int nt = 0; nt < 16; ++nt) {
        acc[nt][0] = __expf(acc[nt][0] - mx0);
        acc[nt][1] = __expf(acc[nt][1] - mx0);
        acc[nt][2] = __expf(acc[nt][2] - mx1);
        acc[nt][3] = __expf(acc[nt][3] - mx1);
        l0 += acc[nt][0] + acc[nt][1];
        l1 += acc[nt][2] + acc[nt][3];
    }
    l0 += __shfl_xor_sync(0xffffffffu, l0, 1);
    l0 += __shfl_xor_sync(0xffffffffu, l0, 2);
    l1 += __shfl_xor_sync(0xffffffffu, l1, 1);
    l1 += __shfl_xor_sync(0xffffffffu, l1, 2);
    const float inv0 = 1.f / l0, inv1 = 1.f / l1;

    __syncthreads();   // all ldmatrix reads of Q/K done before P overwrite

    // ---- store P (tf32) at offset 0, stride 528 B
    {
        uint32_t* p0 = (uint32_t*)(smf + (size_t)r0 * VP_STRIDE) + (lane & 3) * 2;
        uint32_t* p1 = (uint32_t*)(smf + (size_t)(r0 + 8) * VP_STRIDE) + (lane & 3) * 2;
        #pragma unroll
        for (int nt = 0; nt < 16; ++nt) {
            *(uint2*)(p0 + nt * 8) = make_uint2(f2tf32(acc[nt][0]), f2tf32(acc[nt][1]));
            *(uint2*)(p1 + nt * 8) = make_uint2(f2tf32(acc[nt][2]), f2tf32(acc[nt][3]));
        }
    }
    __syncthreads();

    // ---- O = P @ V  (k-steps beyond this warp's causal extent are all-zero P)
    float ao[8][4];
    #pragma unroll
    for (int i = 0; i < 8; ++i)
        #pragma unroll
        for (int c = 0; c < 4; ++c) ao[i][c] = 0.f;

    const int ks_max = 2 * w + 2;          // cols 0 .. 16w+15
    #pragma unroll
    for (int ks = 0; ks < 16; ++ks) {
        if (ks >= ks_max) break;
        uint32_t af[4];
        LDMATRIX_X4(af[0], af[1], af[2], af[3],
                    sb + arow * VP_STRIDE + ks * 32 + akb);
        #pragma unroll
        for (int np = 0; np < 4; ++np) {
            uint32_t bf[4];
            LDMATRIX_X4(bf[0], bf[1], bf[2], bf[3],
                        sb + AT_V + (brow + np * 16) * VP_STRIDE + ks * 32 + bkb);
            MMA_TF32(ao[2*np],   af, (bf));
            MMA_TF32(ao[2*np+1], af, (bf + 2));
        }
    }

    // ---- write O to g_attn[B,T,N,D], tf32-rounded
    {
        const size_t row0 = ((size_t)(b * TT + r0) * NN + n) * DD + head * DH
                          + (lane & 3) * 2;
        const size_t row1 = ((size_t)(b * TT + r0 + 8) * NN + n) * DD + head * DH
                          + (lane & 3) * 2;
        #pragma unroll
        for (int nt = 0; nt < 8; ++nt) {
            *(float2*)(g_attn + row0 + nt * 8) =
                make_float2(tf32round(ao[nt][0] * inv0), tf32round(ao[nt][1] * inv0));
            *(float2*)(g_attn + row1 + nt * 8) =
                make_float2(tf32round(ao[nt][2] * inv1), tf32round(ao[nt][3] * inv1));
        }
    }
}

// ---------------------------------------------------------------------------
extern "C" void kernel_launch(void* const* d_in, const int* in_sizes, int n_in,
                              void* d_out, int out_size)
{
    const float* X   = (const float*)d_in[0];
    const float* STE = (const float*)d_in[1];
    const float* Wq  = (const float*)d_in[2];
    const float* bq  = (const float*)d_in[3];
    const float* Wk  = (const float*)d_in[4];
    const float* bk  = (const float*)d_in[5];
    const float* Wv  = (const float*)d_in[6];
    const float* bv  = (const float*)d_in[7];
    const float* Wo  = (const float*)d_in[8];
    const float* bo  = (const float*)d_in[9];
    float* out = (float*)d_out;

    prep_h<<<MTOT, 384>>>(X, STE);
    prep_w<<<1536 + 512, 384>>>(Wq, Wk, Wv, Wo);

    cudaFuncSetAttribute(gemm2<true>,  cudaFuncAttributeMaxDynamicSharedMemorySize, SMEM_REQ);
    cudaFuncSetAttribute(gemm2<false>, cudaFuncAttributeMaxDynamicSharedMemorySize, SMEM_REQ);
    cudaFuncSetAttribute(attn_tc,      cudaFuncAttributeMaxDynamicSharedMemorySize, AT_SMEM);

    gemm2<true><<<dim3(4, 512, 3), 128, SMEM_REQ>>>(bq, bk, bv, nullptr);
    attn_tc<<<dim3(KH, NN, BB), 256, AT_SMEM>>>();
    gemm2<false><<<dim3(4, 512, 1), 128, SMEM_REQ>>>(bo, bo, bo, out);
}

// round 7
// speedup vs baseline: 4.4187x; 1.0294x over previous
#include <cuda_runtime.h>
#include <math.h>
#include <stdint.h>

// Problem dims
#define BB   8
#define TT   128
#define NN   64
#define KH   8
#define DH   64
#define DD   512
#define MTOT 65536

// Scratch (device globals — allocation-free rule)
__device__ uint32_t g_w[(size_t)3*512*1536];      // tf32-rounded Wq|Wk|Wv bits
__device__ uint32_t g_wo[(size_t)512*512];        // tf32-rounded Wo bits
__device__ float g_q[(size_t)BB*NN*KH*TT*DH];     // [B,N,K,T,d], tf32-rounded
__device__ float g_k[(size_t)BB*NN*KH*TT*DH];
__device__ float g_v[(size_t)BB*NN*KH*TT*DH];
__device__ float g_attn[(size_t)MTOT*DD];         // [B,T,N,D], tf32-rounded

// ---------------------------------------------------------------------------
// Helpers
// ---------------------------------------------------------------------------
__device__ __forceinline__ uint32_t smem_u32(const void* p) {
    uint32_t a;
    asm("{ .reg .u64 t; cvta.to.shared.u64 t, %1; cvt.u32.u64 %0, t; }" : "=r"(a) : "l"(p));
    return a;
}
__device__ __forceinline__ uint32_t f2tf32(float x) {
    uint32_t u;
    asm("cvt.rna.tf32.f32 %0, %1;" : "=r"(u) : "f"(x));
    return u;
}
__device__ __forceinline__ uint32_t u2tf32(uint32_t x) {
    uint32_t u;
    asm("cvt.rna.tf32.f32 %0, %1;" : "=r"(u) : "r"(x));
    return u;
}
__device__ __forceinline__ float tf32round(float x) {
    return __uint_as_float(f2tf32(x));
}

#define CP_ASYNC16(dst, src) \
    asm volatile("cp.async.cg.shared.global [%0], [%1], 16;" :: "r"(dst), "l"(src))
#define CP_COMMIT()  asm volatile("cp.async.commit_group;" ::: "memory")
#define CP_WAIT1()   asm volatile("cp.async.wait_group 1;" ::: "memory")

#define LDMATRIX_X4(r0, r1, r2, r3, addr) \
    asm volatile("ldmatrix.sync.aligned.m8n8.x4.shared.b16 {%0,%1,%2,%3}, [%4];" \
                 : "=r"(r0), "=r"(r1), "=r"(r2), "=r"(r3) : "r"(addr))

#define MMA_TF32(d, a, b) \
    asm volatile("mma.sync.aligned.m16n8k8.row.col.f32.tf32.tf32.f32 " \
                 "{%0,%1,%2,%3}, {%4,%5,%6,%7}, {%8,%9}, {%0,%1,%2,%3};" \
                 : "+f"((d)[0]), "+f"((d)[1]), "+f"((d)[2]), "+f"((d)[3]) \
                 : "r"((a)[0]), "r"((a)[1]), "r"((a)[2]), "r"((a)[3]), \
                   "r"((b)[0]), "r"((b)[1]))

// GEMM SMEM: 3 stages x (A 16KB + B 16KB), bias 2048 B, +1024 align slack
#define STAGE_BYTES 32768
#define OFF_BIAS    98304
#define SMEM_REQ    (98304 + 2048 + 1024)

// Attention SMEM (bytes): Q/K padded stride 272 B, Vt/P stride 528 B
#define AT_Q      0
#define AT_K      34816
#define AT_V      69632
#define AT_SMEM   103424
#define QK_STRIDE 272
#define VP_STRIDE 528

// ---------------------------------------------------------------------------
// Prepass: tf32-round the weights (cheap: 2.6 MB total)
// ---------------------------------------------------------------------------
__global__ __launch_bounds__(384) void prep_w(const float* __restrict__ Wq,
                                              const float* __restrict__ Wk,
                                              const float* __restrict__ Wv,
                                              const float* __restrict__ Wo)
{
    const int b = blockIdx.x;
    if (b < 1536) {
        const int z = b >> 9, n = b & 511;
        const float* W = (z == 0) ? Wq : (z == 1) ? Wk : Wv;
        const int c = threadIdx.x * 4;
        float4 v = *(const float4*)(W + (size_t)n * 1536 + c);
        *(uint4*)(g_w + (size_t)b * 1536 + c) =
            make_uint4(f2tf32(v.x), f2tf32(v.y), f2tf32(v.z), f2tf32(v.w));
    } else {
        const int n = b - 1536;
        if (threadIdx.x < 128) {
            const int c = threadIdx.x * 4;
            float4 v = *(const float4*)(Wo + (size_t)n * 512 + c);
            *(uint4*)(g_wo + (size_t)n * 512 + c) =
                make_uint4(f2tf32(v.x), f2tf32(v.y), f2tf32(v.z), f2tf32(v.w));
        }
    }
}

// ---------------------------------------------------------------------------
// tf32 mma.sync GEMM, cp.async 3-stage, fragment-double-buffered mainloop.
// CTA 128x128x32, 4 warps (2Mx2N), warp tile 64x64.
// B is pre-rounded tf32 bits (g_w/g_wo). A: QKV loads raw fp32 and rounds the
// fragments in registers (cvt.rna) before MMA; proj's A (g_attn) is pre-rounded.
// ---------------------------------------------------------------------------
template<bool QKV>
__global__ __launch_bounds__(128, 2) void gemm2(
    const float* __restrict__ X, const float* __restrict__ STE,
    const float* __restrict__ bias0, const float* __restrict__ bias1,
    const float* __restrict__ bias2, float* __restrict__ dout)
{
    constexpr int KDIM = QKV ? 1536 : 512;
    constexpr int NC   = KDIM / 32;

    extern __shared__ char raw[];
    const uint32_t sb_raw = smem_u32(raw);
    const uint32_t sb0 = (sb_raw + 1023u) & ~1023u;
    char* sm = raw + (sb0 - sb_raw);
    float* s_bias = (float*)(sm + OFF_BIAS);

    const int tid  = threadIdx.x;
    const int lane = tid & 31;
    const int wid  = tid >> 5;
    const int wm   = wid & 1;
    const int wn   = wid >> 1;

    // QKV grid: x = z*4 + ntile (z-adjacent CTAs share the A m-tile in L2)
    const int n0 = QKV ? (blockIdx.x & 3) * 128 : blockIdx.x * 128;
    const int z  = QKV ? (blockIdx.x >> 2) : 0;
    const int m0 = blockIdx.y * 128;

    const float* __restrict__ A = QKV ? X : (const float*)g_attn;
    const float* __restrict__ W = QKV ? (const float*)(g_w + (size_t)z * 512 * 1536)
                                      : (const float*)g_wo;
    const float* __restrict__ bias = (z == 0) ? bias0 : (z == 1) ? bias1 : bias2;

    ((float4*)s_bias)[tid] = ((const float4*)bias)[tid];

    auto issue = [&](int kc, int stage) {
        const uint32_t as = sb0 + stage * STAGE_BYTES;
        const uint32_t bs = as + 16384;
        const int col0 = kc * 32;
        const float* Ap;
        int astride;
        if (QKV) {
            if (col0 < 512) { Ap = A + (size_t)m0 * 512 + col0;            astride = 512; }
            else            { Ap = STE + (size_t)m0 * 1024 + (col0 - 512); astride = 1024; }
        } else              { Ap = A + (size_t)m0 * 512 + col0;            astride = 512; }
        const float* Wp = W + (size_t)n0 * KDIM + col0;
        #pragma unroll
        for (int it = 0; it < 8; ++it) {
            const int pos = tid + it * 128;
            const int row = pos >> 3, c4 = pos & 7;
            const uint32_t d = as + row * 128 + ((c4 * 16) ^ ((row & 7) * 16));
            CP_ASYNC16(d, Ap + (size_t)row * astride + c4 * 4);
        }
        #pragma unroll
        for (int it = 0; it < 8; ++it) {
            const int pos = tid + it * 128;
            const int row = pos >> 3, c4 = pos & 7;
            const uint32_t d = bs + row * 128 + ((c4 * 16) ^ ((row & 7) * 16));
            CP_ASYNC16(d, Wp + (size_t)row * KDIM + c4 * 4);
        }
    };

    float acc[4][8][4];
    #pragma unroll
    for (int i = 0; i < 4; ++i)
        #pragma unroll
        for (int j = 0; j < 8; ++j)
            #pragma unroll
            for (int c = 0; c < 4; ++c) acc[i][j][c] = 0.f;

    const int a_row = wm * 64 + ((lane >> 3) & 1) * 8 + (lane & 7);
    const int a_kb  = (lane >> 4) * 16;
    const int xa    = (a_row & 7) * 16;
    const int b_row = wn * 64 + ((lane >> 4) & 1) * 8 + (lane & 7);
    const int b_kb  = ((lane >> 3) & 1) * 16;
    const int xb    = (b_row & 7) * 16;

    auto compute = [&](int buf) {
        const uint32_t abase = sb0 + buf * STAGE_BYTES;
        const uint32_t bbase = abase + 16384;
        uint32_t af[2][4][4], bf[2][8][2];
        #pragma unroll
        for (int mt = 0; mt < 4; ++mt)
            LDMATRIX_X4(af[0][mt][0], af[0][mt][1], af[0][mt][2], af[0][mt][3],
                        abase + (a_row + mt * 16) * 128 + (a_kb ^ xa));
        #pragma unroll
        for (int np = 0; np < 4; ++np)
            LDMATRIX_X4(bf[0][2*np][0], bf[0][2*np][1], bf[0][2*np+1][0], bf[0][2*np+1][1],
                        bbase + (b_row + np * 16) * 128 + (b_kb ^ xb));
        #pragma unroll
        for (int ks = 0; ks < 4; ++ks) {
            const int cur = ks & 1, nxt = cur ^ 1;
            if (ks < 3) {
                #pragma unroll
                for (int mt = 0; mt < 4; ++mt)
                    LDMATRIX_X4(af[nxt][mt][0], af[nxt][mt][1], af[nxt][mt][2], af[nxt][mt][3],
                                abase + (a_row + mt * 16) * 128 + (((ks + 1) * 32 + a_kb) ^ xa));
                #pragma unroll
                for (int np = 0; np < 4; ++np)
                    LDMATRIX_X4(bf[nxt][2*np][0], bf[nxt][2*np][1],
                                bf[nxt][2*np+1][0], bf[nxt][2*np+1][1],
                                bbase + (b_row + np * 16) * 128 + (((ks + 1) * 32 + b_kb) ^ xb));
            }
            if (QKV) {
                // rna-round the A fragments (raw fp32 from X/STE) before MMA
                #pragma unroll
                for (int mt = 0; mt < 4; ++mt)
                    #pragma unroll
                    for (int r = 0; r < 4; ++r)
                        af[cur][mt][r] = u2tf32(af[cur][mt][r]);
            }
            #pragma unroll
            for (int mt = 0; mt < 4; ++mt)
                #pragma unroll
                for (int nt = 0; nt < 8; ++nt)
                    MMA_TF32(acc[mt][nt], af[cur][mt], bf[cur][nt]);
        }
    };

    issue(0, 0); CP_COMMIT();
    issue(1, 1); CP_COMMIT();

    #pragma unroll 1
    for (int c = 0; c < NC; ++c) {
        CP_WAIT1();
        __syncthreads();
        if (c + 2 < NC) issue(c + 2, (c + 2) % 3);
        CP_COMMIT();
        compute(c % 3);
    }

    float* gq = g_q; float* gk = g_k; float* gv = g_v;
    #pragma unroll
    for (int mt = 0; mt < 4; ++mt) {
        const int R0 = m0 + wm * 64 + mt * 16 + (lane >> 2);
        const int R1 = R0 + 8;
        #pragma unroll
        for (int nt = 0; nt < 8; ++nt) {
            const int o = n0 + wn * 64 + nt * 8 + (lane & 3) * 2;
            const float bx = s_bias[o], by = s_bias[o + 1];
            float v0 = acc[mt][nt][0] + bx; v0 = v0 > 0.f ? v0 : 0.f;
            float v1 = acc[mt][nt][1] + by; v1 = v1 > 0.f ? v1 : 0.f;
            float v2 = acc[mt][nt][2] + bx; v2 = v2 > 0.f ? v2 : 0.f;
            float v3 = acc[mt][nt][3] + by; v3 = v3 > 0.f ? v3 : 0.f;
            if (QKV) {
                v0 = tf32round(v0); v1 = tf32round(v1);
                v2 = tf32round(v2); v3 = tf32round(v3);
                float* outp = (z == 0) ? gq : (z == 1) ? gk : gv;
                const int head = o >> 6, jj = o & 63;
                {
                    const int b_ = R0 >> 13, t_ = (R0 >> 6) & 127, n_ = R0 & 63;
                    const size_t idx = (((size_t)(b_ * NN + n_) * KH + head) * TT + t_) * DH + jj;
                    *(float2*)(outp + idx) = make_float2(v0, v1);
                }
                {
                    const int b_ = R1 >> 13, t_ = (R1 >> 6) & 127, n_ = R1 & 63;
                    const size_t idx = (((size_t)(b_ * NN + n_) * KH + head) * TT + t_) * DH + jj;
                    *(float2*)(outp + idx) = make_float2(v2, v3);
                }
            } else {
                *(float2*)(dout + (size_t)R0 * DD + o) = make_float2(v0, v1);
                *(float2*)(dout + (size_t)R1 * DD + o) = make_float2(v2, v3);
            }
        }
    }
}

// ---------------------------------------------------------------------------
// Tensor-core attention: one CTA per (b,n,head), 256 thr = 8 warps.
// ---------------------------------------------------------------------------
__global__ __launch_bounds__(256, 2) void attn_tc()
{
    extern __shared__ char smf[];
    const uint32_t sb = smem_u32(smf);

    const int head = blockIdx.x;
    const int n    = blockIdx.y;
    const int b    = blockIdx.z;
    const size_t base = ((size_t)(b * NN + n) * KH + head) * (TT * DH);

    const int tid  = threadIdx.x;
    const int lane = tid & 31;
    const int w    = tid >> 5;

    {
        const float4* q4 = (const float4*)(g_q + base);
        const float4* k4 = (const float4*)(g_k + base);
        #pragma unroll
        for (int it = 0; it < 8; ++it) {
            const int pos = tid + it * 256;
            const int t = pos >> 4, d4 = pos & 15;
            *(float4*)(smf + AT_Q + t * QK_STRIDE + d4 * 16) = q4[pos];
            *(float4*)(smf + AT_K + t * QK_STRIDE + d4 * 16) = k4[pos];
        }
        #pragma unroll
        for (int it = 0; it < 8; ++it) {
            const int pos = tid + it * 256;
            const int s = pos & 127, d4 = pos >> 7;
            float4 v = *(const float4*)(g_v + base + (size_t)s * DH + d4 * 4);
            float* vt = (float*)(smf + AT_V) + s;
            vt[(d4 * 4 + 0) * 132] = v.x;
            vt[(d4 * 4 + 1) * 132] = v.y;
            vt[(d4 * 4 + 2) * 132] = v.z;
            vt[(d4 * 4 + 3) * 132] = v.w;
        }
    }
    __syncthreads();

    const int arow = w * 16 + ((lane >> 3) & 1) * 8 + (lane & 7);
    const int akb  = (lane >> 4) * 16;
    const int brow = ((lane >> 4) & 1) * 8 + (lane & 7);
    const int bkb  = ((lane >> 3) & 1) * 16;

    float acc[16][4];
    #pragma unroll
    for (int i = 0; i < 16; ++i)
        #pragma unroll
        for (int c = 0; c < 4; ++c) acc[i][c] = 0.f;

    #pragma unroll
    for (int ks = 0; ks < 8; ++ks) {
        uint32_t af[4];
        LDMATRIX_X4(af[0], af[1], af[2], af[3],
                    sb + AT_Q + arow * QK_STRIDE + ks * 32 + akb);
        #pragma unroll
        for (int np = 0; np < 8; ++np) {
            uint32_t bf[4];
            LDMATRIX_X4(bf[0], bf[1], bf[2], bf[3],
                        sb + AT_K + (brow + np * 16) * QK_STRIDE + ks * 32 + bkb);
            MMA_TF32(acc[2*np],   af, (bf));
            MMA_TF32(acc[2*np+1], af, (bf + 2));
        }
    }

    const int r0 = w * 16 + (lane >> 2);
    float mx0 = -1e30f, mx1 = -1e30f;
    #pragma unroll
    for (int nt = 0; nt < 16; ++nt) {
        const int c0 = nt * 8 + (lane & 3) * 2;
        acc[nt][0] = (c0     <= r0    ) ? acc[nt][0] * 0.125f : -1e30f;
        acc[nt][1] = (c0 + 1 <= r0    ) ? acc[nt][1] * 0.125f : -1e30f;
        acc[nt][2] = (c0     <= r0 + 8) ? acc[nt][2] * 0.125f : -1e30f;
        acc[nt][3] = (c0 + 1 <= r0 + 8) ? acc[nt][3] * 0.125f : -1e30f;
        mx0 = fmaxf(mx0, fmaxf(acc[nt][0], acc[nt][1]));
        mx1 = fmaxf(mx1, fmaxf(acc[nt][2], acc[nt][3]));
    }
    mx0 = fmaxf(mx0, __shfl_xor_sync(0xffffffffu, mx0, 1));
    mx0 = fmaxf(mx0, __shfl_xor_sync(0xffffffffu, mx0, 2));
    mx1 = fmaxf(mx1, __shfl_xor_sync(0xffffffffu, mx1, 1));
    mx1 = fmaxf(mx1, __shfl_xor_sync(0xffffffffu, mx1, 2));

    float l0 = 0.f, l1 = 0.f;
    #pragma unroll
    for (int nt = 0; nt < 16; ++nt) {
        acc[nt][0] = __expf(acc[nt][0] - mx0);
        acc[nt][1] = __expf(acc[nt][1] - mx0);
        acc[nt][2] = __expf(acc[nt][2] - mx1);
        acc[nt][3] = __expf(acc[nt][3] - mx1);
        l0 += acc[nt][0] + acc[nt][1];
        l1 += acc[nt][2] + acc[nt][3];
    }
    l0 += __shfl_xor_sync(0xffffffffu, l0, 1);
    l0 += __shfl_xor_sync(0xffffffffu, l0, 2);
    l1 += __shfl_xor_sync(0xffffffffu, l1, 1);
    l1 += __shfl_xor_sync(0xffffffffu, l1, 2);
    const float inv0 = 1.f / l0, inv1 = 1.f / l1;

    __syncthreads();

    {
        uint32_t* p0 = (uint32_t*)(smf + (size_t)r0 * VP_STRIDE) + (lane & 3) * 2;
        uint32_t* p1 = (uint32_t*)(smf + (size_t)(r0 + 8) * VP_STRIDE) + (lane & 3) * 2;
        #pragma unroll
        for (int nt = 0; nt < 16; ++nt) {
            *(uint2*)(p0 + nt * 8) = make_uint2(f2tf32(acc[nt][0]), f2tf32(acc[nt][1]));
            *(uint2*)(p1 + nt * 8) = make_uint2(f2tf32(acc[nt][2]), f2tf32(acc[nt][3]));
        }
    }
    __syncthreads();

    float ao[8][4];
    #pragma unroll
    for (int i = 0; i < 8; ++i)
        #pragma unroll
        for (int c = 0; c < 4; ++c) ao[i][c] = 0.f;

    const int ks_max = 2 * w + 2;
    #pragma unroll
    for (int ks = 0; ks < 16; ++ks) {
        if (ks >= ks_max) break;
        uint32_t af[4];
        LDMATRIX_X4(af[0], af[1], af[2], af[3],
                    sb + arow * VP_STRIDE + ks * 32 + akb);
        #pragma unroll
        for (int np = 0; np < 4; ++np) {
            uint32_t bf[4];
            LDMATRIX_X4(bf[0], bf[1], bf[2], bf[3],
                        sb + AT_V + (brow + np * 16) * VP_STRIDE + ks * 32 + bkb);
            MMA_TF32(ao[2*np],   af, (bf));
            MMA_TF32(ao[2*np+1], af, (bf + 2));
        }
    }

    {
        const size_t row0 = ((size_t)(b * TT + r0) * NN + n) * DD + head * DH
                          + (lane & 3) * 2;
        const size_t row1 = ((size_t)(b * TT + r0 + 8) * NN + n) * DD + head * DH
                          + (lane & 3) * 2;
        #pragma unroll
        for (int nt = 0; nt < 8; ++nt) {
            *(float2*)(g_attn + row0 + nt * 8) =
                make_float2(tf32round(ao[nt][0] * inv0), tf32round(ao[nt][1] * inv0));
            *(float2*)(g_attn + row1 + nt * 8) =
                make_float2(tf32round(ao[nt][2] * inv1), tf32round(ao[nt][3] * inv1));
        }
    }
}

// ---------------------------------------------------------------------------
extern "C" void kernel_launch(void* const* d_in, const int* in_sizes, int n_in,
                              void* d_out, int out_size)
{
    const float* X   = (const float*)d_in[0];
    const float* STE = (const float*)d_in[1];
    const float* Wq  = (const float*)d_in[2];
    const float* bq  = (const float*)d_in[3];
    const float* Wk  = (const float*)d_in[4];
    const float* bk  = (const float*)d_in[5];
    const float* Wv  = (const float*)d_in[6];
    const float* bv  = (const float*)d_in[7];
    const float* Wo  = (const float*)d_in[8];
    const float* bo  = (const float*)d_in[9];
    float* out = (float*)d_out;

    cudaFuncSetAttribute(gemm2<true>,  cudaFuncAttributeMaxDynamicSharedMemorySize, SMEM_REQ);
    cudaFuncSetAttribute(gemm2<false>, cudaFuncAttributeMaxDynamicSharedMemorySize, SMEM_REQ);
    cudaFuncSetAttribute(attn_tc,      cudaFuncAttributeMaxDynamicSharedMemorySize, AT_SMEM);

    prep_w<<<1536 + 512, 384>>>(Wq, Wk, Wv, Wo);

    // QKV: grid (z*4+ntile, mtile) — z-adjacent CTAs reuse the A m-tile in L2
    gemm2<true><<<dim3(12, 512), 128, SMEM_REQ>>>(X, STE, bq, bk, bv, nullptr);
    attn_tc<<<dim3(KH, NN, BB), 256, AT_SMEM>>>();
    gemm2<false><<<dim3(4, 512), 128, SMEM_REQ>>>(nullptr, nullptr, bo, bo, bo, out);
}

// round 8
// speedup vs baseline: 4.4575x; 1.0088x over previous
#include <cuda_runtime.h>
#include <math.h>
#include <stdint.h>

// Problem dims
#define BB   8
#define TT   128
#define NN   64
#define KH   8
#define DH   64
#define DD   512
#define MTOT 65536

// Scratch (device globals — allocation-free rule)
__device__ uint32_t g_w[(size_t)3*512*1536];      // tf32-rounded Wq|Wk|Wv bits
__device__ uint32_t g_wo[(size_t)512*512];        // tf32-rounded Wo bits
__device__ float g_q[(size_t)BB*NN*KH*TT*DH];     // [B,N,K,T,d], tf32-rounded
__device__ float g_k[(size_t)BB*NN*KH*TT*DH];
__device__ float g_v[(size_t)BB*NN*KH*TT*DH];
__device__ float g_attn[(size_t)MTOT*DD];         // [B,T,N,D], tf32-rounded

// ---------------------------------------------------------------------------
// Helpers
// ---------------------------------------------------------------------------
__device__ __forceinline__ uint32_t smem_u32(const void* p) {
    uint32_t a;
    asm("{ .reg .u64 t; cvta.to.shared.u64 t, %1; cvt.u32.u64 %0, t; }" : "=r"(a) : "l"(p));
    return a;
}
__device__ __forceinline__ uint32_t f2tf32(float x) {
    uint32_t u;
    asm("cvt.rna.tf32.f32 %0, %1;" : "=r"(u) : "f"(x));
    return u;
}
__device__ __forceinline__ uint32_t u2tf32(uint32_t x) {
    uint32_t u;
    asm("cvt.rna.tf32.f32 %0, %1;" : "=r"(u) : "r"(x));
    return u;
}
__device__ __forceinline__ float tf32round(float x) {
    return __uint_as_float(f2tf32(x));
}

#define CP_ASYNC16(dst, src) \
    asm volatile("cp.async.cg.shared.global [%0], [%1], 16;" :: "r"(dst), "l"(src))
#define CP_COMMIT()  asm volatile("cp.async.commit_group;" ::: "memory")
#define CP_WAIT2()   asm volatile("cp.async.wait_group 2;" ::: "memory")
#define CP_WAIT0()   asm volatile("cp.async.wait_group 0;" ::: "memory")

#define LDMATRIX_X4(r0, r1, r2, r3, addr) \
    asm volatile("ldmatrix.sync.aligned.m8n8.x4.shared.b16 {%0,%1,%2,%3}, [%4];" \
                 : "=r"(r0), "=r"(r1), "=r"(r2), "=r"(r3) : "r"(addr))

#define MMA_TF32(d, a, b) \
    asm volatile("mma.sync.aligned.m16n8k8.row.col.f32.tf32.tf32.f32 " \
                 "{%0,%1,%2,%3}, {%4,%5,%6,%7}, {%8,%9}, {%0,%1,%2,%3};" \
                 : "+f"((d)[0]), "+f"((d)[1]), "+f"((d)[2]), "+f"((d)[3]) \
                 : "r"((a)[0]), "r"((a)[1]), "r"((a)[2]), "r"((a)[3]), \
                   "r"((b)[0]), "r"((b)[1]))

// GEMM SMEM: 3 stages x (A 16KB + B 16KB), bias 2048 B, +1024 align slack
#define STAGE_BYTES 32768
#define OFF_BIAS    98304
#define SMEM_REQ    (98304 + 2048 + 1024)

// Attention SMEM (bytes): Q/K padded stride 272 B, Vt/P stride 528 B
#define AT_Q      0
#define AT_K      34816
#define AT_V      69632
#define AT_SMEM   103424
#define QK_STRIDE 272
#define VP_STRIDE 528

// ---------------------------------------------------------------------------
// Prepass: tf32-round the weights (cheap: 2.6 MB total)
// ---------------------------------------------------------------------------
__global__ __launch_bounds__(384) void prep_w(const float* __restrict__ Wq,
                                              const float* __restrict__ Wk,
                                              const float* __restrict__ Wv,
                                              const float* __restrict__ Wo)
{
    const int b = blockIdx.x;
    if (b < 1536) {
        const int z = b >> 9, n = b & 511;
        const float* W = (z == 0) ? Wq : (z == 1) ? Wk : Wv;
        const int c = threadIdx.x * 4;
        float4 v = *(const float4*)(W + (size_t)n * 1536 + c);
        *(uint4*)(g_w + (size_t)b * 1536 + c) =
            make_uint4(f2tf32(v.x), f2tf32(v.y), f2tf32(v.z), f2tf32(v.w));
    } else {
        const int n = b - 1536;
        if (threadIdx.x < 128) {
            const int c = threadIdx.x * 4;
            float4 v = *(const float4*)(Wo + (size_t)n * 512 + c);
            *(uint4*)(g_wo + (size_t)n * 512 + c) =
                make_uint4(f2tf32(v.x), f2tf32(v.y), f2tf32(v.z), f2tf32(v.w));
        }
    }
}

// ---------------------------------------------------------------------------
// tf32 mma.sync GEMM, cp.async 3-stage, fragment-double-buffered mainloop.
// CTA 128x128x32, 4 warps (2Mx2N), warp tile 64x64.
// Loop order per chunk: publish-barrier -> issue(c+2) -> wait(c) -> barrier
// -> compute(c). Issue burst overlaps the memory wait.
// ---------------------------------------------------------------------------
template<bool QKV>
__global__ __launch_bounds__(128, 2) void gemm2(
    const float* __restrict__ X, const float* __restrict__ STE,
    const float* __restrict__ bias0, const float* __restrict__ bias1,
    const float* __restrict__ bias2, float* __restrict__ dout)
{
    constexpr int KDIM = QKV ? 1536 : 512;
    constexpr int NC   = KDIM / 32;

    extern __shared__ char raw[];
    const uint32_t sb_raw = smem_u32(raw);
    const uint32_t sb0 = (sb_raw + 1023u) & ~1023u;
    char* sm = raw + (sb0 - sb_raw);
    float* s_bias = (float*)(sm + OFF_BIAS);

    const int tid  = threadIdx.x;
    const int lane = tid & 31;
    const int wid  = tid >> 5;
    const int wm   = wid & 1;
    const int wn   = wid >> 1;

    const int n0 = QKV ? (blockIdx.x & 3) * 128 : blockIdx.x * 128;
    const int z  = QKV ? (blockIdx.x >> 2) : 0;
    const int m0 = blockIdx.y * 128;

    const float* __restrict__ A = QKV ? X : (const float*)g_attn;
    const float* __restrict__ W = QKV ? (const float*)(g_w + (size_t)z * 512 * 1536)
                                      : (const float*)g_wo;
    const float* __restrict__ bias = (z == 0) ? bias0 : (z == 1) ? bias1 : bias2;

    ((float4*)s_bias)[tid] = ((const float4*)bias)[tid];

    auto issue = [&](int kc, int stage) {
        const uint32_t as = sb0 + stage * STAGE_BYTES;
        const uint32_t bs = as + 16384;
        const int col0 = kc * 32;
        const float* Ap;
        int astride;
        if (QKV) {
            if (col0 < 512) { Ap = A + (size_t)m0 * 512 + col0;            astride = 512; }
            else            { Ap = STE + (size_t)m0 * 1024 + (col0 - 512); astride = 1024; }
        } else              { Ap = A + (size_t)m0 * 512 + col0;            astride = 512; }
        const float* Wp = W + (size_t)n0 * KDIM + col0;
        #pragma unroll
        for (int it = 0; it < 8; ++it) {
            const int pos = tid + it * 128;
            const int row = pos >> 3, c4 = pos & 7;
            const uint32_t d = as + row * 128 + ((c4 * 16) ^ ((row & 7) * 16));
            CP_ASYNC16(d, Ap + (size_t)row * astride + c4 * 4);
        }
        #pragma unroll
        for (int it = 0; it < 8; ++it) {
            const int pos = tid + it * 128;
            const int row = pos >> 3, c4 = pos & 7;
            const uint32_t d = bs + row * 128 + ((c4 * 16) ^ ((row & 7) * 16));
            CP_ASYNC16(d, Wp + (size_t)row * KDIM + c4 * 4);
        }
    };

    float acc[4][8][4];
    #pragma unroll
    for (int i = 0; i < 4; ++i)
        #pragma unroll
        for (int j = 0; j < 8; ++j)
            #pragma unroll
            for (int c = 0; c < 4; ++c) acc[i][j][c] = 0.f;

    const int a_row = wm * 64 + ((lane >> 3) & 1) * 8 + (lane & 7);
    const int a_kb  = (lane >> 4) * 16;
    const int xa    = (a_row & 7) * 16;
    const int b_row = wn * 64 + ((lane >> 4) & 1) * 8 + (lane & 7);
    const int b_kb  = ((lane >> 3) & 1) * 16;
    const int xb    = (b_row & 7) * 16;

    auto compute = [&](int buf) {
        const uint32_t abase = sb0 + buf * STAGE_BYTES;
        const uint32_t bbase = abase + 16384;
        uint32_t af[2][4][4], bf[2][8][2];
        #pragma unroll
        for (int mt = 0; mt < 4; ++mt) {
            LDMATRIX_X4(af[0][mt][0], af[0][mt][1], af[0][mt][2], af[0][mt][3],
                        abase + (a_row + mt * 16) * 128 + (a_kb ^ xa));
            if (QKV) {
                #pragma unroll
                for (int r = 0; r < 4; ++r) af[0][mt][r] = u2tf32(af[0][mt][r]);
            }
        }
        #pragma unroll
        for (int np = 0; np < 4; ++np)
            LDMATRIX_X4(bf[0][2*np][0], bf[0][2*np][1], bf[0][2*np+1][0], bf[0][2*np+1][1],
                        bbase + (b_row + np * 16) * 128 + (b_kb ^ xb));
        #pragma unroll
        for (int ks = 0; ks < 4; ++ks) {
            const int cur = ks & 1, nxt = cur ^ 1;
            if (ks < 3) {
                #pragma unroll
                for (int mt = 0; mt < 4; ++mt) {
                    LDMATRIX_X4(af[nxt][mt][0], af[nxt][mt][1], af[nxt][mt][2], af[nxt][mt][3],
                                abase + (a_row + mt * 16) * 128 + (((ks + 1) * 32 + a_kb) ^ xa));
                    if (QKV) {
                        #pragma unroll
                        for (int r = 0; r < 4; ++r) af[nxt][mt][r] = u2tf32(af[nxt][mt][r]);
                    }
                }
                #pragma unroll
                for (int np = 0; np < 4; ++np)
                    LDMATRIX_X4(bf[nxt][2*np][0], bf[nxt][2*np][1],
                                bf[nxt][2*np+1][0], bf[nxt][2*np+1][1],
                                bbase + (b_row + np * 16) * 128 + (((ks + 1) * 32 + b_kb) ^ xb));
            }
            #pragma unroll
            for (int mt = 0; mt < 4; ++mt)
                #pragma unroll
                for (int nt = 0; nt < 8; ++nt)
                    MMA_TF32(acc[mt][nt], af[cur][mt], bf[cur][nt]);
        }
    };

    issue(0, 0); CP_COMMIT();
    issue(1, 1); CP_COMMIT();

    #pragma unroll 1
    for (int c = 0; c < NC; ++c) {
        __syncthreads();                 // all warps done reading stage (c+2)%3
        if (c + 2 < NC) issue(c + 2, (c + 2) % 3);
        CP_COMMIT();
        CP_WAIT2();                      // chunk c landed (3 groups pending max)
        __syncthreads();                 // publish chunk c
        compute(c % 3);
    }

    float* gq = g_q; float* gk = g_k; float* gv = g_v;
    #pragma unroll
    for (int mt = 0; mt < 4; ++mt) {
        const int R0 = m0 + wm * 64 + mt * 16 + (lane >> 2);
        const int R1 = R0 + 8;
        #pragma unroll
        for (int nt = 0; nt < 8; ++nt) {
            const int o = n0 + wn * 64 + nt * 8 + (lane & 3) * 2;
            const float bx = s_bias[o], by = s_bias[o + 1];
            float v0 = acc[mt][nt][0] + bx; v0 = v0 > 0.f ? v0 : 0.f;
            float v1 = acc[mt][nt][1] + by; v1 = v1 > 0.f ? v1 : 0.f;
            float v2 = acc[mt][nt][2] + bx; v2 = v2 > 0.f ? v2 : 0.f;
            float v3 = acc[mt][nt][3] + by; v3 = v3 > 0.f ? v3 : 0.f;
            if (QKV) {
                v0 = tf32round(v0); v1 = tf32round(v1);
                v2 = tf32round(v2); v3 = tf32round(v3);
                float* outp = (z == 0) ? gq : (z == 1) ? gk : gv;
                const int head = o >> 6, jj = o & 63;
                {
                    const int b_ = R0 >> 13, t_ = (R0 >> 6) & 127, n_ = R0 & 63;
                    const size_t idx = (((size_t)(b_ * NN + n_) * KH + head) * TT + t_) * DH + jj;
                    *(float2*)(outp + idx) = make_float2(v0, v1);
                }
                {
                    const int b_ = R1 >> 13, t_ = (R1 >> 6) & 127, n_ = R1 & 63;
                    const size_t idx = (((size_t)(b_ * NN + n_) * KH + head) * TT + t_) * DH + jj;
                    *(float2*)(outp + idx) = make_float2(v2, v3);
                }
            } else {
                *(float2*)(dout + (size_t)R0 * DD + o) = make_float2(v0, v1);
                *(float2*)(dout + (size_t)R1 * DD + o) = make_float2(v2, v3);
            }
        }
    }
}

// ---------------------------------------------------------------------------
// Tensor-core attention: one CTA per (b,n,head), 256 thr = 8 warps.
// Q/K staged via cp.async (overlapped with V register-transpose).
// ---------------------------------------------------------------------------
__global__ __launch_bounds__(256, 2) void attn_tc()
{
    extern __shared__ char smf[];
    const uint32_t sb = smem_u32(smf);

    const int head = blockIdx.x;
    const int n    = blockIdx.y;
    const int b    = blockIdx.z;
    const size_t base = ((size_t)(b * NN + n) * KH + head) * (TT * DH);

    const int tid  = threadIdx.x;
    const int lane = tid & 31;
    const int w    = tid >> 5;

    // Q/K via cp.async
    {
        const float* qg = g_q + base;
        const float* kg = g_k + base;
        #pragma unroll
        for (int it = 0; it < 8; ++it) {
            const int pos = tid + it * 256;
            const int t = pos >> 4, d4 = pos & 15;
            CP_ASYNC16(sb + AT_Q + t * QK_STRIDE + d4 * 16, qg + (size_t)pos * 4);
            CP_ASYNC16(sb + AT_K + t * QK_STRIDE + d4 * 16, kg + (size_t)pos * 4);
        }
        CP_COMMIT();
        // V transpose through registers (overlaps the cp.async latency)
        #pragma unroll
        for (int it = 0; it < 8; ++it) {
            const int pos = tid + it * 256;
            const int s = pos & 127, d4 = pos >> 7;
            float4 v = *(const float4*)(g_v + base + (size_t)s * DH + d4 * 4);
            float* vt = (float*)(smf + AT_V) + s;
            vt[(d4 * 4 + 0) * 132] = v.x;
            vt[(d4 * 4 + 1) * 132] = v.y;
            vt[(d4 * 4 + 2) * 132] = v.z;
            vt[(d4 * 4 + 3) * 132] = v.w;
        }
        CP_WAIT0();
    }
    __syncthreads();

    const int arow = w * 16 + ((lane >> 3) & 1) * 8 + (lane & 7);
    const int akb  = (lane >> 4) * 16;
    const int brow = ((lane >> 4) & 1) * 8 + (lane & 7);
    const int bkb  = ((lane >> 3) & 1) * 16;

    float acc[16][4];
    #pragma unroll
    for (int i = 0; i < 16; ++i)
        #pragma unroll
        for (int c = 0; c < 4; ++c) acc[i][c] = 0.f;

    #pragma unroll
    for (int ks = 0; ks < 8; ++ks) {
        uint32_t af[4];
        LDMATRIX_X4(af[0], af[1], af[2], af[3],
                    sb + AT_Q + arow * QK_STRIDE + ks * 32 + akb);
        #pragma unroll
        for (int np = 0; np < 8; ++np) {
            uint32_t bf[4];
            LDMATRIX_X4(bf[0], bf[1], bf[2], bf[3],
                        sb + AT_K + (brow + np * 16) * QK_STRIDE + ks * 32 + bkb);
            MMA_TF32(acc[2*np],   af, (bf));
            MMA_TF32(acc[2*np+1], af, (bf + 2));
        }
    }

    const int r0 = w * 16 + (lane >> 2);
    float mx0 = -1e30f, mx1 = -1e30f;
    #pragma unroll
    for (int nt = 0; nt < 16; ++nt) {
        const int c0 = nt * 8 + (lane & 3) * 2;
        acc[nt][0] = (c0     <= r0    ) ? acc[nt][0] * 0.125f : -1e30f;
        acc[nt][1] = (c0 + 1 <= r0    ) ? acc[nt][1] * 0.125f : -1e30f;
        acc[nt][2] = (c0     <= r0 + 8) ? acc[nt][2] * 0.125f : -1e30f;
        acc[nt][3] = (c0 + 1 <= r0 + 8) ? acc[nt][3] * 0.125f : -1e30f;
        mx0 = fmaxf(mx0, fmaxf(acc[nt][0], acc[nt][1]));
        mx1 = fmaxf(mx1, fmaxf(acc[nt][2], acc[nt][3]));
    }
    mx0 = fmaxf(mx0, __shfl_xor_sync(0xffffffffu, mx0, 1));
    mx0 = fmaxf(mx0, __shfl_xor_sync(0xffffffffu, mx0, 2));
    mx1 = fmaxf(mx1, __shfl_xor_sync(0xffffffffu, mx1, 1));
    mx1 = fmaxf(mx1, __shfl_xor_sync(0xffffffffu, mx1, 2));

    float l0 = 0.f, l1 = 0.f;
    #pragma unroll
    for (int nt = 0; nt < 16; ++nt) {
        acc[nt][0] = __expf(acc[nt][0] - mx0);
        acc[nt][1] = __expf(acc[nt][1] - mx0);
        acc[nt][2] = __expf(acc[nt][2] - mx1);
        acc[nt][3] = __expf(acc[nt][3] - mx1);
        l0 += acc[nt][0] + acc[nt][1];
        l1 += acc[nt][2] + acc[nt][3];
    }
    l0 += __shfl_xor_sync(0xffffffffu, l0, 1);
    l0 += __shfl_xor_sync(0xffffffffu, l0, 2);
    l1 += __shfl_xor_sync(0xffffffffu, l1, 1);
    l1 += __shfl_xor_sync(0xffffffffu, l1, 2);
    const float inv0 = 1.f / l0, inv1 = 1.f / l1;

    __syncthreads();

    {
        uint32_t* p0 = (uint32_t*)(smf + (size_t)r0 * VP_STRIDE) + (lane & 3) * 2;
        uint32_t* p1 = (uint32_t*)(smf + (size_t)(r0 + 8) * VP_STRIDE) + (lane & 3) * 2;
        #pragma unroll
        for (int nt = 0; nt < 16; ++nt) {
            *(uint2*)(p0 + nt * 8) = make_uint2(f2tf32(acc[nt][0]), f2tf32(acc[nt][1]));
            *(uint2*)(p1 + nt * 8) = make_uint2(f2tf32(acc[nt][2]), f2tf32(acc[nt][3]));
        }
    }
    __syncthreads();

    float ao[8][4];
    #pragma unroll
    for (int i = 0; i < 8; ++i)
        #pragma unroll
        for (int c = 0; c < 4; ++c) ao[i][c] = 0.f;

    const int ks_max = 2 * w + 2;
    #pragma unroll
    for (int ks = 0; ks < 16; ++ks) {
        if (ks >= ks_max) break;
        uint32_t af[4];
        LDMATRIX_X4(af[0], af[1], af[2], af[3],
                    sb + arow * VP_STRIDE + ks * 32 + akb);
        #pragma unroll
        for (int np = 0; np < 4; ++np) {
            uint32_t bf[4];
            LDMATRIX_X4(bf[0], bf[1], bf[2], bf[3],
                        sb + AT_V + (brow + np * 16) * VP_STRIDE + ks * 32 + bkb);
            MMA_TF32(ao[2*np],   af, (bf));
            MMA_TF32(ao[2*np+1], af, (bf + 2));
        }
    }

    {
        const size_t row0 = ((size_t)(b * TT + r0) * NN + n) * DD + head * DH
                          + (lane & 3) * 2;
        const size_t row1 = ((size_t)(b * TT + r0 + 8) * NN + n) * DD + head * DH
                          + (lane & 3) * 2;
        #pragma unroll
        for (int nt = 0; nt < 8; ++nt) {
            *(float2*)(g_attn + row0 + nt * 8) =
                make_float2(tf32round(ao[nt][0] * inv0), tf32round(ao[nt][1] * inv0));
            *(float2*)(g_attn + row1 + nt * 8) =
                make_float2(tf32round(ao[nt][2] * inv1), tf32round(ao[nt][3] * inv1));
        }
    }
}

// ---------------------------------------------------------------------------
extern "C" void kernel_launch(void* const* d_in, const int* in_sizes, int n_in,
                              void* d_out, int out_size)
{
    const float* X   = (const float*)d_in[0];
    const float* STE = (const float*)d_in[1];
    const float* Wq  = (const float*)d_in[2];
    const float* bq  = (const float*)d_in[3];
    const float* Wk  = (const float*)d_in[4];
    const float* bk  = (const float*)d_in[5];
    const float* Wv  = (const float*)d_in[6];
    const float* bv  = (const float*)d_in[7];
    const float* Wo  = (const float*)d_in[8];
    const float* bo  = (const float*)d_in[9];
    float* out = (float*)d_out;

    cudaFuncSetAttribute(gemm2<true>,  cudaFuncAttributeMaxDynamicSharedMemorySize, SMEM_REQ);
    cudaFuncSetAttribute(gemm2<false>, cudaFuncAttributeMaxDynamicSharedMemorySize, SMEM_REQ);
    cudaFuncSetAttribute(attn_tc,      cudaFuncAttributeMaxDynamicSharedMemorySize, AT_SMEM);

    prep_w<<<1536 + 512, 384>>>(Wq, Wk, Wv, Wo);

    // QKV: grid (z*4+ntile, mtile) — z-adjacent CTAs reuse the A m-tile in L2
    gemm2<true><<<dim3(12, 512), 128, SMEM_REQ>>>(X, STE, bq, bk, bv, nullptr);
    attn_tc<<<dim3(KH, NN, BB), 256, AT_SMEM>>>();
    gemm2<false><<<dim3(4, 512), 128, SMEM_REQ>>>(nullptr, nullptr, bo, bo, bo, out);
}

// round 9
// speedup vs baseline: 7.4294x; 1.6667x over previous
#include <cuda_runtime.h>
#include <cuda_fp16.h>
#include <math.h>
#include <stdint.h>

// Problem dims
#define BB   8
#define TT   128
#define NN   64
#define KH   8
#define DH   64
#define DD   512
#define MTOT 65536

// Scratch (device globals — allocation-free rule)
__device__ __align__(16) __half g_h[(size_t)MTOT*1536];    // fp16 concat(X,STE)
__device__ __align__(16) __half g_w[(size_t)3*512*1536];   // fp16 Wq|Wk|Wv
__device__ __align__(16) __half g_wo[(size_t)512*512];     // fp16 Wo
__device__ __align__(16) __half g_q[(size_t)BB*NN*KH*TT*DH];  // [B,N,K,T,d]
__device__ __align__(16) __half g_k[(size_t)BB*NN*KH*TT*DH];
__device__ __align__(16) __half g_v[(size_t)BB*NN*KH*TT*DH];
__device__ __align__(16) __half g_attn[(size_t)MTOT*DD];   // [B,T,N,D]

// ---------------------------------------------------------------------------
// Helpers
// ---------------------------------------------------------------------------
__device__ __forceinline__ uint32_t smem_u32(const void* p) {
    uint32_t a;
    asm("{ .reg .u64 t; cvta.to.shared.u64 t, %1; cvt.u32.u64 %0, t; }" : "=r"(a) : "l"(p));
    return a;
}

#define CP_ASYNC16(dst, src) \
    asm volatile("cp.async.cg.shared.global [%0], [%1], 16;" :: "r"(dst), "l"(src))
#define CP_COMMIT()  asm volatile("cp.async.commit_group;" ::: "memory")
#define CP_WAIT2()   asm volatile("cp.async.wait_group 2;" ::: "memory")
#define CP_WAIT0()   asm volatile("cp.async.wait_group 0;" ::: "memory")

#define LDMATRIX_X4(r0, r1, r2, r3, addr) \
    asm volatile("ldmatrix.sync.aligned.m8n8.x4.shared.b16 {%0,%1,%2,%3}, [%4];" \
                 : "=r"(r0), "=r"(r1), "=r"(r2), "=r"(r3) : "r"(addr))

#define LDMATRIX_X4_T(r0, r1, r2, r3, addr) \
    asm volatile("ldmatrix.sync.aligned.m8n8.x4.trans.shared.b16 {%0,%1,%2,%3}, [%4];" \
                 : "=r"(r0), "=r"(r1), "=r"(r2), "=r"(r3) : "r"(addr))

#define MMA_F16(d, a, b0, b1) \
    asm volatile("mma.sync.aligned.m16n8k16.row.col.f32.f16.f16.f32 " \
                 "{%0,%1,%2,%3}, {%4,%5,%6,%7}, {%8,%9}, {%0,%1,%2,%3};" \
                 : "+f"((d)[0]), "+f"((d)[1]), "+f"((d)[2]), "+f"((d)[3]) \
                 : "r"((a)[0]), "r"((a)[1]), "r"((a)[2]), "r"((a)[3]), \
                   "r"(b0), "r"(b1))

// GEMM SMEM: 3 stages x (A 16KB + B 16KB), bias 2048 B, +1024 align slack
#define STAGE_BYTES 32768
#define OFF_BIAS    98304
#define SMEM_REQ    (98304 + 2048 + 1024)

// Attention SMEM: Q,K,V 16KB each (128 rows x 128B swizzled), P 32KB (256B rows)
#define AT_Q    0
#define AT_K    16384
#define AT_V    32768
#define AT_P    49152
#define AT_SMEM 81920

// ---------------------------------------------------------------------------
// Prepass: fp16 conversions
// ---------------------------------------------------------------------------
__global__ __launch_bounds__(384) void prep_h(const float* __restrict__ X,
                                              const float* __restrict__ STE)
{
    const int row = blockIdx.x;
    const int c   = threadIdx.x * 4;
    float4 v;
    if (c < 512) v = *(const float4*)(X + (size_t)row * 512 + c);
    else         v = *(const float4*)(STE + (size_t)row * 1024 + (c - 512));
    __half2* dst = (__half2*)(g_h + (size_t)row * 1536 + c);
    dst[0] = __floats2half2_rn(v.x, v.y);
    dst[1] = __floats2half2_rn(v.z, v.w);
}

__global__ __launch_bounds__(384) void prep_w(const float* __restrict__ Wq,
                                              const float* __restrict__ Wk,
                                              const float* __restrict__ Wv,
                                              const float* __restrict__ Wo)
{
    const int b = blockIdx.x;
    if (b < 1536) {
        const int z = b >> 9, n = b & 511;
        const float* W = (z == 0) ? Wq : (z == 1) ? Wk : Wv;
        const int c = threadIdx.x * 4;
        float4 v = *(const float4*)(W + (size_t)n * 1536 + c);
        __half2* dst = (__half2*)(g_w + (size_t)b * 1536 + c);
        dst[0] = __floats2half2_rn(v.x, v.y);
        dst[1] = __floats2half2_rn(v.z, v.w);
    } else {
        const int n = b - 1536;
        if (threadIdx.x < 128) {
            const int c = threadIdx.x * 4;
            float4 v = *(const float4*)(Wo + (size_t)n * 512 + c);
            __half2* dst = (__half2*)(g_wo + (size_t)n * 512 + c);
            dst[0] = __floats2half2_rn(v.x, v.y);
            dst[1] = __floats2half2_rn(v.z, v.w);
        }
    }
}

// ---------------------------------------------------------------------------
// fp16 mma.sync GEMM (m16n8k16), cp.async 3-stage, fragment double-buffered.
// CTA 128x128x64, 4 warps (2Mx2N), warp tile 64x64.
// QKV=true : A=g_h (K=1536), W=g_w[z], fp16 scatter into g_q/g_k/g_v
// QKV=false: A=g_attn (K=512), W=g_wo, fp32 epilogue into dout
// ---------------------------------------------------------------------------
template<bool QKV>
__global__ __launch_bounds__(128, 2) void gemm3(
    const float* __restrict__ bias0, const float* __restrict__ bias1,
    const float* __restrict__ bias2, float* __restrict__ dout)
{
    constexpr int KDIM = QKV ? 1536 : 512;
    constexpr int NC   = KDIM / 64;

    extern __shared__ char raw[];
    const uint32_t sb_raw = smem_u32(raw);
    const uint32_t sb0 = (sb_raw + 1023u) & ~1023u;
    char* sm = raw + (sb0 - sb_raw);
    float* s_bias = (float*)(sm + OFF_BIAS);

    const int tid  = threadIdx.x;
    const int lane = tid & 31;
    const int wid  = tid >> 5;
    const int wm   = wid & 1;
    const int wn   = wid >> 1;

    const int n0 = QKV ? (blockIdx.x & 3) * 128 : blockIdx.x * 128;
    const int z  = QKV ? (blockIdx.x >> 2) : 0;
    const int m0 = blockIdx.y * 128;

    const __half* __restrict__ A = QKV ? g_h : g_attn;
    const __half* __restrict__ W = QKV ? (g_w + (size_t)z * 512 * 1536) : g_wo;
    const float* __restrict__ bias = (z == 0) ? bias0 : (z == 1) ? bias1 : bias2;

    ((float4*)s_bias)[tid] = ((const float4*)bias)[tid];

    auto issue = [&](int kc, int stage) {
        const uint32_t as = sb0 + stage * STAGE_BYTES;
        const uint32_t bs = as + 16384;
        const __half* Ap = A + (size_t)m0 * KDIM + kc * 64;
        const __half* Wp = W + (size_t)n0 * KDIM + kc * 64;
        #pragma unroll
        for (int it = 0; it < 8; ++it) {
            const int pos = tid + it * 128;
            const int row = pos >> 3, c8 = pos & 7;
            const uint32_t d = as + row * 128 + ((c8 * 16) ^ ((row & 7) * 16));
            CP_ASYNC16(d, Ap + (size_t)row * KDIM + c8 * 8);
        }
        #pragma unroll
        for (int it = 0; it < 8; ++it) {
            const int pos = tid + it * 128;
            const int row = pos >> 3, c8 = pos & 7;
            const uint32_t d = bs + row * 128 + ((c8 * 16) ^ ((row & 7) * 16));
            CP_ASYNC16(d, Wp + (size_t)row * KDIM + c8 * 8);
        }
    };

    float acc[4][8][4];
    #pragma unroll
    for (int i = 0; i < 4; ++i)
        #pragma unroll
        for (int j = 0; j < 8; ++j)
            #pragma unroll
            for (int c = 0; c < 4; ++c) acc[i][j][c] = 0.f;

    const int a_row = wm * 64 + ((lane >> 3) & 1) * 8 + (lane & 7);
    const int a_kb  = (lane >> 4) * 16;
    const int xa    = (a_row & 7) * 16;
    const int b_row = wn * 64 + ((lane >> 3) & 1) * 8 + (lane & 7);
    const int b_kb  = (lane >> 4) * 16;
    const int xb    = (b_row & 7) * 16;

    auto compute = [&](int buf) {
        const uint32_t abase = sb0 + buf * STAGE_BYTES;
        const uint32_t bbase = abase + 16384;
        uint32_t af[2][4][4], bf[2][4][4];
        #pragma unroll
        for (int mt = 0; mt < 4; ++mt)
            LDMATRIX_X4(af[0][mt][0], af[0][mt][1], af[0][mt][2], af[0][mt][3],
                        abase + (a_row + mt * 16) * 128 + (a_kb ^ xa));
        #pragma unroll
        for (int np = 0; np < 4; ++np)
            LDMATRIX_X4(bf[0][np][0], bf[0][np][1], bf[0][np][2], bf[0][np][3],
                        bbase + (b_row + np * 16) * 128 + (b_kb ^ xb));
        #pragma unroll
        for (int ks = 0; ks < 4; ++ks) {
            const int cur = ks & 1, nxt = cur ^ 1;
            if (ks < 3) {
                #pragma unroll
                for (int mt = 0; mt < 4; ++mt)
                    LDMATRIX_X4(af[nxt][mt][0], af[nxt][mt][1], af[nxt][mt][2], af[nxt][mt][3],
                                abase + (a_row + mt * 16) * 128 + (((ks + 1) * 32 + a_kb) ^ xa));
                #pragma unroll
                for (int np = 0; np < 4; ++np)
                    LDMATRIX_X4(bf[nxt][np][0], bf[nxt][np][1], bf[nxt][np][2], bf[nxt][np][3],
                                bbase + (b_row + np * 16) * 128 + (((ks + 1) * 32 + b_kb) ^ xb));
            }
            #pragma unroll
            for (int mt = 0; mt < 4; ++mt)
                #pragma unroll
                for (int np = 0; np < 4; ++np) {
                    MMA_F16(acc[mt][2*np],   af[cur][mt], bf[cur][np][0], bf[cur][np][2]);
                    MMA_F16(acc[mt][2*np+1], af[cur][mt], bf[cur][np][1], bf[cur][np][3]);
                }
        }
    };

    issue(0, 0); CP_COMMIT();
    issue(1, 1); CP_COMMIT();

    #pragma unroll 1
    for (int c = 0; c < NC; ++c) {
        __syncthreads();
        if (c + 2 < NC) issue(c + 2, (c + 2) % 3);
        CP_COMMIT();
        CP_WAIT2();
        __syncthreads();
        compute(c % 3);
    }

    __half* gq = g_q; __half* gk = g_k; __half* gv = g_v;
    #pragma unroll
    for (int mt = 0; mt < 4; ++mt) {
        const int R0 = m0 + wm * 64 + mt * 16 + (lane >> 2);
        const int R1 = R0 + 8;
        #pragma unroll
        for (int nt = 0; nt < 8; ++nt) {
            const int o = n0 + wn * 64 + nt * 8 + (lane & 3) * 2;
            const float bx = s_bias[o], by = s_bias[o + 1];
            float v0 = acc[mt][nt][0] + bx; v0 = v0 > 0.f ? v0 : 0.f;
            float v1 = acc[mt][nt][1] + by; v1 = v1 > 0.f ? v1 : 0.f;
            float v2 = acc[mt][nt][2] + bx; v2 = v2 > 0.f ? v2 : 0.f;
            float v3 = acc[mt][nt][3] + by; v3 = v3 > 0.f ? v3 : 0.f;
            if (QKV) {
                __half* outp = (z == 0) ? gq : (z == 1) ? gk : gv;
                const int head = o >> 6, jj = o & 63;
                {
                    const int b_ = R0 >> 13, t_ = (R0 >> 6) & 127, n_ = R0 & 63;
                    const size_t idx = (((size_t)(b_ * NN + n_) * KH + head) * TT + t_) * DH + jj;
                    *(__half2*)(outp + idx) = __floats2half2_rn(v0, v1);
                }
                {
                    const int b_ = R1 >> 13, t_ = (R1 >> 6) & 127, n_ = R1 & 63;
                    const size_t idx = (((size_t)(b_ * NN + n_) * KH + head) * TT + t_) * DH + jj;
                    *(__half2*)(outp + idx) = __floats2half2_rn(v2, v3);
                }
            } else {
                *(float2*)(dout + (size_t)R0 * DD + o) = make_float2(v0, v1);
                *(float2*)(dout + (size_t)R1 * DD + o) = make_float2(v2, v3);
            }
        }
    }
}

// ---------------------------------------------------------------------------
// fp16 tensor-core attention: one CTA per (b,n,head), 256 thr = 8 warps.
// Q,K,V in 128B swizzled rows; V consumed via ldmatrix.trans (no transpose).
// ---------------------------------------------------------------------------
__global__ __launch_bounds__(256, 2) void attn_tc()
{
    extern __shared__ char smf[];
    const uint32_t sb = smem_u32(smf);

    const int head = blockIdx.x;
    const int n    = blockIdx.y;
    const int b    = blockIdx.z;
    const size_t base = ((size_t)(b * NN + n) * KH + head) * (TT * DH);

    const int tid  = threadIdx.x;
    const int lane = tid & 31;
    const int w    = tid >> 5;

    // Load Q, K, V: each 128 rows x 64 halves (128B) with xor-swizzle
    {
        const __half* qg = g_q + base;
        const __half* kg = g_k + base;
        const __half* vg = g_v + base;
        #pragma unroll
        for (int it = 0; it < 4; ++it) {
            const int pos = tid + it * 256;
            const int r = pos >> 3, c8 = pos & 7;
            const uint32_t off = r * 128 + ((c8 * 16) ^ ((r & 7) * 16));
            CP_ASYNC16(sb + AT_Q + off, qg + (size_t)pos * 8);
            CP_ASYNC16(sb + AT_K + off, kg + (size_t)pos * 8);
            CP_ASYNC16(sb + AT_V + off, vg + (size_t)pos * 8);
        }
        CP_COMMIT();
        CP_WAIT0();
    }
    __syncthreads();

    const int arow = w * 16 + ((lane >> 3) & 1) * 8 + (lane & 7);
    const int akb  = (lane >> 4) * 16;
    const int xa   = (arow & 7) * 16;
    const int brow8 = ((lane >> 3) & 1) * 8 + (lane & 7);
    const int bkb   = (lane >> 4) * 16;

    // ---- S = Q K^T : ks 0..3 (k16 each)
    float acc[16][4];
    #pragma unroll
    for (int i = 0; i < 16; ++i)
        #pragma unroll
        for (int c = 0; c < 4; ++c) acc[i][c] = 0.f;

    #pragma unroll
    for (int ks = 0; ks < 4; ++ks) {
        uint32_t af[4];
        LDMATRIX_X4(af[0], af[1], af[2], af[3],
                    sb + AT_Q + arow * 128 + ((ks * 32 + akb) ^ xa));
        #pragma unroll
        for (int np = 0; np < 8; ++np) {
            const int srow = np * 16 + brow8;
            uint32_t bf[4];
            LDMATRIX_X4(bf[0], bf[1], bf[2], bf[3],
                        sb + AT_K + srow * 128 + ((ks * 32 + bkb) ^ ((srow & 7) * 16)));
            MMA_F16(acc[2*np],   af, bf[0], bf[2]);
            MMA_F16(acc[2*np+1], af, bf[1], bf[3]);
        }
    }

    // ---- softmax (rows r0, r0+8)
    const int r0 = w * 16 + (lane >> 2);
    float mx0 = -1e30f, mx1 = -1e30f;
    #pragma unroll
    for (int nt = 0; nt < 16; ++nt) {
        const int c0 = nt * 8 + (lane & 3) * 2;
        acc[nt][0] = (c0     <= r0    ) ? acc[nt][0] * 0.125f : -1e30f;
        acc[nt][1] = (c0 + 1 <= r0    ) ? acc[nt][1] * 0.125f : -1e30f;
        acc[nt][2] = (c0     <= r0 + 8) ? acc[nt][2] * 0.125f : -1e30f;
        acc[nt][3] = (c0 + 1 <= r0 + 8) ? acc[nt][3] * 0.125f : -1e30f;
        mx0 = fmaxf(mx0, fmaxf(acc[nt][0], acc[nt][1]));
        mx1 = fmaxf(mx1, fmaxf(acc[nt][2], acc[nt][3]));
    }
    mx0 = fmaxf(mx0, __shfl_xor_sync(0xffffffffu, mx0, 1));
    mx0 = fmaxf(mx0, __shfl_xor_sync(0xffffffffu, mx0, 2));
    mx1 = fmaxf(mx1, __shfl_xor_sync(0xffffffffu, mx1, 1));
    mx1 = fmaxf(mx1, __shfl_xor_sync(0xffffffffu, mx1, 2));

    float l0 = 0.f, l1 = 0.f;
    #pragma unroll
    for (int nt = 0; nt < 16; ++nt) {
        acc[nt][0] = __expf(acc[nt][0] - mx0);
        acc[nt][1] = __expf(acc[nt][1] - mx0);
        acc[nt][2] = __expf(acc[nt][2] - mx1);
        acc[nt][3] = __expf(acc[nt][3] - mx1);
        l0 += acc[nt][0] + acc[nt][1];
        l1 += acc[nt][2] + acc[nt][3];
    }
    l0 += __shfl_xor_sync(0xffffffffu, l0, 1);
    l0 += __shfl_xor_sync(0xffffffffu, l0, 2);
    l1 += __shfl_xor_sync(0xffffffffu, l1, 1);
    l1 += __shfl_xor_sync(0xffffffffu, l1, 2);
    const float inv0 = 1.f / l0, inv1 = 1.f / l1;

    // ---- store P fp16: rows 256B, xor-swizzled 16B chunks
    {
        const uint32_t p0 = sb + AT_P + r0 * 256;
        const uint32_t p1 = sb + AT_P + (r0 + 8) * 256;
        const int cb = (lane & 3) * 4;
        const int x0 = (r0 & 7) * 16, x1 = ((r0 + 8) & 7) * 16;
        #pragma unroll
        for (int nt = 0; nt < 16; ++nt) {
            __half2 h0 = __floats2half2_rn(acc[nt][0], acc[nt][1]);
            __half2 h1 = __floats2half2_rn(acc[nt][2], acc[nt][3]);
            *(__half2*)(smf + (p0 - sb) + ((nt * 16 + cb) ^ x0)) = h0;
            *(__half2*)(smf + (p1 - sb) + ((nt * 16 + cb) ^ x1)) = h1;
        }
    }
    __syncwarp();   // warp reads only its own P rows below

    // ---- O = P @ V : ks 0..7 (s16 each), causal: ks <= w
    float ao[8][4];
    #pragma unroll
    for (int i = 0; i < 8; ++i)
        #pragma unroll
        for (int c = 0; c < 4; ++c) ao[i][c] = 0.f;

    const int ks_max = w + 1;
    #pragma unroll 1
    for (int ks = 0; ks < ks_max; ++ks) {
        uint32_t af[4];
        LDMATRIX_X4(af[0], af[1], af[2], af[3],
                    sb + AT_P + arow * 256 + ((ks * 32 + akb) ^ xa));
        #pragma unroll
        for (int np = 0; np < 4; ++np) {
            const int srow = ks * 16 + brow8;
            uint32_t bf[4];
            LDMATRIX_X4_T(bf[0], bf[1], bf[2], bf[3],
                          sb + AT_V + srow * 128 + ((np * 32 + bkb) ^ ((srow & 7) * 16)));
            MMA_F16(ao[2*np],   af, bf[0], bf[1]);
            MMA_F16(ao[2*np+1], af, bf[2], bf[3]);
        }
    }

    // ---- write O fp16 to g_attn[B,T,N,D]
    {
        const size_t row0 = ((size_t)(b * TT + r0) * NN + n) * DD + head * DH
                          + (lane & 3) * 2;
        const size_t row1 = ((size_t)(b * TT + r0 + 8) * NN + n) * DD + head * DH
                          + (lane & 3) * 2;
        #pragma unroll
        for (int nt = 0; nt < 8; ++nt) {
            *(__half2*)(g_attn + row0 + nt * 8) =
                __floats2half2_rn(ao[nt][0] * inv0, ao[nt][1] * inv0);
            *(__half2*)(g_attn + row1 + nt * 8) =
                __floats2half2_rn(ao[nt][2] * inv1, ao[nt][3] * inv1);
        }
    }
}

// ---------------------------------------------------------------------------
extern "C" void kernel_launch(void* const* d_in, const int* in_sizes, int n_in,
                              void* d_out, int out_size)
{
    const float* X   = (const float*)d_in[0];
    const float* STE = (const float*)d_in[1];
    const float* Wq  = (const float*)d_in[2];
    const float* bq  = (const float*)d_in[3];
    const float* Wk  = (const float*)d_in[4];
    const float* bk  = (const float*)d_in[5];
    const float* Wv  = (const float*)d_in[6];
    const float* bv  = (const float*)d_in[7];
    const float* Wo  = (const float*)d_in[8];
    const float* bo  = (const float*)d_in[9];
    float* out = (float*)d_out;

    cudaFuncSetAttribute(gemm3<true>,  cudaFuncAttributeMaxDynamicSharedMemorySize, SMEM_REQ);
    cudaFuncSetAttribute(gemm3<false>, cudaFuncAttributeMaxDynamicSharedMemorySize, SMEM_REQ);
    cudaFuncSetAttribute(attn_tc,      cudaFuncAttributeMaxDynamicSharedMemorySize, AT_SMEM);

    prep_h<<<MTOT, 384>>>(X, STE);
    prep_w<<<1536 + 512, 384>>>(Wq, Wk, Wv, Wo);

    // QKV: grid (z*4+ntile, mtile) — z-adjacent CTAs reuse the A m-tile in L2
    gemm3<true><<<dim3(12, 512), 128, SMEM_REQ>>>(bq, bk, bv, nullptr);
    attn_tc<<<dim3(KH, NN, BB), 256, AT_SMEM>>>();
    gemm3<false><<<dim3(4, 512), 128, SMEM_REQ>>>(bo, bo, bo, out);
}

// round 10
// speedup vs baseline: 7.7571x; 1.0441x over previous
#include <cuda_runtime.h>
#include <cuda_fp16.h>
#include <math.h>
#include <stdint.h>

// Problem dims
#define BB   8
#define TT   128
#define NN   64
#define KH   8
#define DH   64
#define DD   512
#define MTOT 65536

// Scratch (device globals — allocation-free rule)
__device__ __align__(16) __half g_h[(size_t)MTOT*1536];    // fp16 concat(X,STE)
__device__ __align__(16) __half g_w[(size_t)3*512*1536];   // fp16 Wq|Wk|Wv
__device__ __align__(16) __half g_wo[(size_t)512*512];     // fp16 Wo
__device__ __align__(16) __half g_q[(size_t)BB*NN*KH*TT*DH];  // [B,N,K,T,d]
__device__ __align__(16) __half g_k[(size_t)BB*NN*KH*TT*DH];
__device__ __align__(16) __half g_v[(size_t)BB*NN*KH*TT*DH];
__device__ __align__(16) __half g_attn[(size_t)MTOT*DD];   // [B,T,N,D]

// ---------------------------------------------------------------------------
// Helpers
// ---------------------------------------------------------------------------
__device__ __forceinline__ uint32_t smem_u32(const void* p) {
    uint32_t a;
    asm("{ .reg .u64 t; cvta.to.shared.u64 t, %1; cvt.u32.u64 %0, t; }" : "=r"(a) : "l"(p));
    return a;
}

#define CP_ASYNC16(dst, src) \
    asm volatile("cp.async.cg.shared.global [%0], [%1], 16;" :: "r"(dst), "l"(src))
#define CP_COMMIT()  asm volatile("cp.async.commit_group;" ::: "memory")
#define CP_WAIT1()   asm volatile("cp.async.wait_group 1;" ::: "memory")
#define CP_WAIT0()   asm volatile("cp.async.wait_group 0;" ::: "memory")

#define LDMATRIX_X4(r0, r1, r2, r3, addr) \
    asm volatile("ldmatrix.sync.aligned.m8n8.x4.shared.b16 {%0,%1,%2,%3}, [%4];" \
                 : "=r"(r0), "=r"(r1), "=r"(r2), "=r"(r3) : "r"(addr))

#define LDMATRIX_X4_T(r0, r1, r2, r3, addr) \
    asm volatile("ldmatrix.sync.aligned.m8n8.x4.trans.shared.b16 {%0,%1,%2,%3}, [%4];" \
                 : "=r"(r0), "=r"(r1), "=r"(r2), "=r"(r3) : "r"(addr))

#define MMA_F16(d, a, b0, b1) \
    asm volatile("mma.sync.aligned.m16n8k16.row.col.f32.f16.f16.f32 " \
                 "{%0,%1,%2,%3}, {%4,%5,%6,%7}, {%8,%9}, {%0,%1,%2,%3};" \
                 : "+f"((d)[0]), "+f"((d)[1]), "+f"((d)[2]), "+f"((d)[3]) \
                 : "r"((a)[0]), "r"((a)[1]), "r"((a)[2]), "r"((a)[3]), \
                   "r"(b0), "r"(b1))

// GEMM SMEM: 2 stages x (A 16KB + B 16KB) = 64KB, bias 2048 B, +1024 align slack
#define STAGE_BYTES 32768
#define OFF_BIAS    65536
#define SMEM_REQ    (65536 + 2048 + 1024)

// Attention SMEM: Q,K,V 16KB each (128 rows x 128B swizzled), P 32KB (256B rows)
#define AT_Q    0
#define AT_K    16384
#define AT_V    32768
#define AT_P    49152
#define AT_SMEM 81920

// ---------------------------------------------------------------------------
// Prepass: fp16 conversions
// ---------------------------------------------------------------------------
__global__ __launch_bounds__(384) void prep_h(const float* __restrict__ X,
                                              const float* __restrict__ STE)
{
    const int row = blockIdx.x;
    const int c   = threadIdx.x * 4;
    float4 v;
    if (c < 512) v = *(const float4*)(X + (size_t)row * 512 + c);
    else         v = *(const float4*)(STE + (size_t)row * 1024 + (c - 512));
    __half2* dst = (__half2*)(g_h + (size_t)row * 1536 + c);
    dst[0] = __floats2half2_rn(v.x, v.y);
    dst[1] = __floats2half2_rn(v.z, v.w);
}

__global__ __launch_bounds__(384) void prep_w(const float* __restrict__ Wq,
                                              const float* __restrict__ Wk,
                                              const float* __restrict__ Wv,
                                              const float* __restrict__ Wo)
{
    const int b = blockIdx.x;
    if (b < 1536) {
        const int z = b >> 9, n = b & 511;
        const float* W = (z == 0) ? Wq : (z == 1) ? Wk : Wv;
        const int c = threadIdx.x * 4;
        float4 v = *(const float4*)(W + (size_t)n * 1536 + c);
        __half2* dst = (__half2*)(g_w + (size_t)b * 1536 + c);
        dst[0] = __floats2half2_rn(v.x, v.y);
        dst[1] = __floats2half2_rn(v.z, v.w);
    } else {
        const int n = b - 1536;
        if (threadIdx.x < 128) {
            const int c = threadIdx.x * 4;
            float4 v = *(const float4*)(Wo + (size_t)n * 512 + c);
            __half2* dst = (__half2*)(g_wo + (size_t)n * 512 + c);
            dst[0] = __floats2half2_rn(v.x, v.y);
            dst[1] = __floats2half2_rn(v.z, v.w);
        }
    }
}

// ---------------------------------------------------------------------------
// fp16 mma.sync GEMM (m16n8k16), cp.async 2-stage, 3 CTAs/SM (12 warps/SM).
// CTA 128x128x64, 4 warps (2Mx2N), warp tile 64x64. Single-buffered fragments
// (register budget for occupancy 3). Cross-CTA overlap hides pipeline bubbles.
// QKV=true : A=g_h (K=1536), W=g_w[z], fp16 scatter into g_q/g_k/g_v
// QKV=false: A=g_attn (K=512), W=g_wo, fp32 epilogue into dout
// ---------------------------------------------------------------------------
template<bool QKV>
__global__ __launch_bounds__(128, 3) void gemm3(
    const float* __restrict__ bias0, const float* __restrict__ bias1,
    const float* __restrict__ bias2, float* __restrict__ dout)
{
    constexpr int KDIM = QKV ? 1536 : 512;
    constexpr int NC   = KDIM / 64;

    extern __shared__ char raw[];
    const uint32_t sb_raw = smem_u32(raw);
    const uint32_t sb0 = (sb_raw + 1023u) & ~1023u;
    char* sm = raw + (sb0 - sb_raw);
    float* s_bias = (float*)(sm + OFF_BIAS);

    const int tid  = threadIdx.x;
    const int lane = tid & 31;
    const int wid  = tid >> 5;
    const int wm   = wid & 1;
    const int wn   = wid >> 1;

    const int n0 = QKV ? (blockIdx.x & 3) * 128 : blockIdx.x * 128;
    const int z  = QKV ? (blockIdx.x >> 2) : 0;
    const int m0 = blockIdx.y * 128;

    const __half* __restrict__ A = QKV ? g_h : g_attn;
    const __half* __restrict__ W = QKV ? (g_w + (size_t)z * 512 * 1536) : g_wo;
    const float* __restrict__ bias = (z == 0) ? bias0 : (z == 1) ? bias1 : bias2;

    ((float4*)s_bias)[tid] = ((const float4*)bias)[tid];

    auto issue = [&](int kc, int stage) {
        const uint32_t as = sb0 + stage * STAGE_BYTES;
        const uint32_t bs = as + 16384;
        const __half* Ap = A + (size_t)m0 * KDIM + kc * 64;
        const __half* Wp = W + (size_t)n0 * KDIM + kc * 64;
        #pragma unroll
        for (int it = 0; it < 8; ++it) {
            const int pos = tid + it * 128;
            const int row = pos >> 3, c8 = pos & 7;
            const uint32_t d = as + row * 128 + ((c8 * 16) ^ ((row & 7) * 16));
            CP_ASYNC16(d, Ap + (size_t)row * KDIM + c8 * 8);
        }
        #pragma unroll
        for (int it = 0; it < 8; ++it) {
            const int pos = tid + it * 128;
            const int row = pos >> 3, c8 = pos & 7;
            const uint32_t d = bs + row * 128 + ((c8 * 16) ^ ((row & 7) * 16));
            CP_ASYNC16(d, Wp + (size_t)row * KDIM + c8 * 8);
        }
    };

    float acc[4][8][4];
    #pragma unroll
    for (int i = 0; i < 4; ++i)
        #pragma unroll
        for (int j = 0; j < 8; ++j)
            #pragma unroll
            for (int c = 0; c < 4; ++c) acc[i][j][c] = 0.f;

    const int a_row = wm * 64 + ((lane >> 3) & 1) * 8 + (lane & 7);
    const int a_kb  = (lane >> 4) * 16;
    const int xa    = (a_row & 7) * 16;
    const int b_row = wn * 64 + ((lane >> 3) & 1) * 8 + (lane & 7);
    const int b_kb  = (lane >> 4) * 16;
    const int xb    = (b_row & 7) * 16;

    auto compute = [&](int buf) {
        const uint32_t abase = sb0 + buf * STAGE_BYTES;
        const uint32_t bbase = abase + 16384;
        #pragma unroll
        for (int ks = 0; ks < 4; ++ks) {
            uint32_t af[4][4], bf[4][4];
            #pragma unroll
            for (int mt = 0; mt < 4; ++mt)
                LDMATRIX_X4(af[mt][0], af[mt][1], af[mt][2], af[mt][3],
                            abase + (a_row + mt * 16) * 128 + ((ks * 32 + a_kb) ^ xa));
            #pragma unroll
            for (int np = 0; np < 4; ++np)
                LDMATRIX_X4(bf[np][0], bf[np][1], bf[np][2], bf[np][3],
                            bbase + (b_row + np * 16) * 128 + ((ks * 32 + b_kb) ^ xb));
            #pragma unroll
            for (int mt = 0; mt < 4; ++mt)
                #pragma unroll
                for (int np = 0; np < 4; ++np) {
                    MMA_F16(acc[mt][2*np],   af[mt], bf[np][0], bf[np][2]);
                    MMA_F16(acc[mt][2*np+1], af[mt], bf[np][1], bf[np][3]);
                }
        }
    };

    issue(0, 0); CP_COMMIT();
    issue(1, 1); CP_COMMIT();

    #pragma unroll 1
    for (int c = 0; c < NC; ++c) {
        if (c + 1 < NC) { CP_WAIT1(); } else { CP_WAIT0(); }
        __syncthreads();                 // publish chunk c
        compute(c & 1);
        __syncthreads();                 // all warps done reading stage c&1
        if (c + 2 < NC) { issue(c + 2, c & 1); CP_COMMIT(); }
    }

    __half* gq = g_q; __half* gk = g_k; __half* gv = g_v;
    #pragma unroll
    for (int mt = 0; mt < 4; ++mt) {
        const int R0 = m0 + wm * 64 + mt * 16 + (lane >> 2);
        const int R1 = R0 + 8;
        #pragma unroll
        for (int nt = 0; nt < 8; ++nt) {
            const int o = n0 + wn * 64 + nt * 8 + (lane & 3) * 2;
            const float bx = s_bias[o], by = s_bias[o + 1];
            float v0 = acc[mt][nt][0] + bx; v0 = v0 > 0.f ? v0 : 0.f;
            float v1 = acc[mt][nt][1] + by; v1 = v1 > 0.f ? v1 : 0.f;
            float v2 = acc[mt][nt][2] + bx; v2 = v2 > 0.f ? v2 : 0.f;
            float v3 = acc[mt][nt][3] + by; v3 = v3 > 0.f ? v3 : 0.f;
            if (QKV) {
                __half* outp = (z == 0) ? gq : (z == 1) ? gk : gv;
                const int head = o >> 6, jj = o & 63;
                {
                    const int b_ = R0 >> 13, t_ = (R0 >> 6) & 127, n_ = R0 & 63;
                    const size_t idx = (((size_t)(b_ * NN + n_) * KH + head) * TT + t_) * DH + jj;
                    *(__half2*)(outp + idx) = __floats2half2_rn(v0, v1);
                }
                {
                    const int b_ = R1 >> 13, t_ = (R1 >> 6) & 127, n_ = R1 & 63;
                    const size_t idx = (((size_t)(b_ * NN + n_) * KH + head) * TT + t_) * DH + jj;
                    *(__half2*)(outp + idx) = __floats2half2_rn(v2, v3);
                }
            } else {
                *(float2*)(dout + (size_t)R0 * DD + o) = make_float2(v0, v1);
                *(float2*)(dout + (size_t)R1 * DD + o) = make_float2(v2, v3);
            }
        }
    }
}

// ---------------------------------------------------------------------------
// fp16 tensor-core attention: one CTA per (b,n,head), 256 thr = 8 warps.
// Q,K,V in 128B swizzled rows; V consumed via ldmatrix.trans (no transpose).
// ---------------------------------------------------------------------------
__global__ __launch_bounds__(256, 2) void attn_tc()
{
    extern __shared__ char smf[];
    const uint32_t sb = smem_u32(smf);

    const int head = blockIdx.x;
    const int n    = blockIdx.y;
    const int b    = blockIdx.z;
    const size_t base = ((size_t)(b * NN + n) * KH + head) * (TT * DH);

    const int tid  = threadIdx.x;
    const int lane = tid & 31;
    const int w    = tid >> 5;

    {
        const __half* qg = g_q + base;
        const __half* kg = g_k + base;
        const __half* vg = g_v + base;
        #pragma unroll
        for (int it = 0; it < 4; ++it) {
            const int pos = tid + it * 256;
            const int r = pos >> 3, c8 = pos & 7;
            const uint32_t off = r * 128 + ((c8 * 16) ^ ((r & 7) * 16));
            CP_ASYNC16(sb + AT_Q + off, qg + (size_t)pos * 8);
            CP_ASYNC16(sb + AT_K + off, kg + (size_t)pos * 8);
            CP_ASYNC16(sb + AT_V + off, vg + (size_t)pos * 8);
        }
        CP_COMMIT();
        CP_WAIT0();
    }
    __syncthreads();

    const int arow = w * 16 + ((lane >> 3) & 1) * 8 + (lane & 7);
    const int akb  = (lane >> 4) * 16;
    const int xa   = (arow & 7) * 16;
    const int brow8 = ((lane >> 3) & 1) * 8 + (lane & 7);
    const int bkb   = (lane >> 4) * 16;

    float acc[16][4];
    #pragma unroll
    for (int i = 0; i < 16; ++i)
        #pragma unroll
        for (int c = 0; c < 4; ++c) acc[i][c] = 0.f;

    #pragma unroll
    for (int ks = 0; ks < 4; ++ks) {
        uint32_t af[4];
        LDMATRIX_X4(af[0], af[1], af[2], af[3],
                    sb + AT_Q + arow * 128 + ((ks * 32 + akb) ^ xa));
        #pragma unroll
        for (int np = 0; np < 8; ++np) {
            const int srow = np * 16 + brow8;
            uint32_t bf[4];
            LDMATRIX_X4(bf[0], bf[1], bf[2], bf[3],
                        sb + AT_K + srow * 128 + ((ks * 32 + bkb) ^ ((srow & 7) * 16)));
            MMA_F16(acc[2*np],   af, bf[0], bf[2]);
            MMA_F16(acc[2*np+1], af, bf[1], bf[3]);
        }
    }

    const int r0 = w * 16 + (lane >> 2);
    float mx0 = -1e30f, mx1 = -1e30f;
    #pragma unroll
    for (int nt = 0; nt < 16; ++nt) {
        const int c0 = nt * 8 + (lane & 3) * 2;
        acc[nt][0] = (c0     <= r0    ) ? acc[nt][0] * 0.125f : -1e30f;
        acc[nt][1] = (c0 + 1 <= r0    ) ? acc[nt][1] * 0.125f : -1e30f;
        acc[nt][2] = (c0     <= r0 + 8) ? acc[nt][2] * 0.125f : -1e30f;
        acc[nt][3] = (c0 + 1 <= r0 + 8) ? acc[nt][3] * 0.125f : -1e30f;
        mx0 = fmaxf(mx0, fmaxf(acc[nt][0], acc[nt][1]));
        mx1 = fmaxf(mx1, fmaxf(acc[nt][2], acc[nt][3]));
    }
    mx0 = fmaxf(mx0, __shfl_xor_sync(0xffffffffu, mx0, 1));
    mx0 = fmaxf(mx0, __shfl_xor_sync(0xffffffffu, mx0, 2));
    mx1 = fmaxf(mx1, __shfl_xor_sync(0xffffffffu, mx1, 1));
    mx1 = fmaxf(mx1, __shfl_xor_sync(0xffffffffu, mx1, 2));

    float l0 = 0.f, l1 = 0.f;
    #pragma unroll
    for (int nt = 0; nt < 16; ++nt) {
        acc[nt][0] = __expf(acc[nt][0] - mx0);
        acc[nt][1] = __expf(acc[nt][1] - mx0);
        acc[nt][2] = __expf(acc[nt][2] - mx1);
        acc[nt][3] = __expf(acc[nt][3] - mx1);
        l0 += acc[nt][0] + acc[nt][1];
        l1 += acc[nt][2] + acc[nt][3];
    }
    l0 += __shfl_xor_sync(0xffffffffu, l0, 1);
    l0 += __shfl_xor_sync(0xffffffffu, l0, 2);
    l1 += __shfl_xor_sync(0xffffffffu, l1, 1);
    l1 += __shfl_xor_sync(0xffffffffu, l1, 2);
    const float inv0 = 1.f / l0, inv1 = 1.f / l1;

    {
        const uint32_t p0 = sb + AT_P + r0 * 256;
        const uint32_t p1 = sb + AT_P + (r0 + 8) * 256;
        const int cb = (lane & 3) * 4;
        const int x0 = (r0 & 7) * 16, x1 = ((r0 + 8) & 7) * 16;
        #pragma unroll
        for (int nt = 0; nt < 16; ++nt) {
            __half2 h0 = __floats2half2_rn(acc[nt][0], acc[nt][1]);
            __half2 h1 = __floats2half2_rn(acc[nt][2], acc[nt][3]);
            *(__half2*)(smf + (p0 - sb) + ((nt * 16 + cb) ^ x0)) = h0;
            *(__half2*)(smf + (p1 - sb) + ((nt * 16 + cb) ^ x1)) = h1;
        }
    }
    __syncwarp();   // warp reads only its own P rows below

    float ao[8][4];
    #pragma unroll
    for (int i = 0; i < 8; ++i)
        #pragma unroll
        for (int c = 0; c < 4; ++c) ao[i][c] = 0.f;

    const int ks_max = w + 1;
    #pragma unroll 1
    for (int ks = 0; ks < ks_max; ++ks) {
        uint32_t af[4];
        LDMATRIX_X4(af[0], af[1], af[2], af[3],
                    sb + AT_P + arow * 256 + ((ks * 32 + akb) ^ xa));
        #pragma unroll
        for (int np = 0; np < 4; ++np) {
            const int srow = ks * 16 + brow8;
            uint32_t bf[4];
            LDMATRIX_X4_T(bf[0], bf[1], bf[2], bf[3],
                          sb + AT_V + srow * 128 + ((np * 32 + bkb) ^ ((srow & 7) * 16)));
            MMA_F16(ao[2*np],   af, bf[0], bf[1]);
            MMA_F16(ao[2*np+1], af, bf[2], bf[3]);
        }
    }

    {
        const size_t row0 = ((size_t)(b * TT + r0) * NN + n) * DD + head * DH
                          + (lane & 3) * 2;
        const size_t row1 = ((size_t)(b * TT + r0 + 8) * NN + n) * DD + head * DH
                          + (lane & 3) * 2;
        #pragma unroll
        for (int nt = 0; nt < 8; ++nt) {
            *(__half2*)(g_attn + row0 + nt * 8) =
                __floats2half2_rn(ao[nt][0] * inv0, ao[nt][1] * inv0);
            *(__half2*)(g_attn + row1 + nt * 8) =
                __floats2half2_rn(ao[nt][2] * inv1, ao[nt][3] * inv1);
        }
    }
}

// ---------------------------------------------------------------------------
extern "C" void kernel_launch(void* const* d_in, const int* in_sizes, int n_in,
                              void* d_out, int out_size)
{
    const float* X   = (const float*)d_in[0];
    const float* STE = (const float*)d_in[1];
    const float* Wq  = (const float*)d_in[2];
    const float* bq  = (const float*)d_in[3];
    const float* Wk  = (const float*)d_in[4];
    const float* bk  = (const float*)d_in[5];
    const float* Wv  = (const float*)d_in[6];
    const float* bv  = (const float*)d_in[7];
    const float* Wo  = (const float*)d_in[8];
    const float* bo  = (const float*)d_in[9];
    float* out = (float*)d_out;

    cudaFuncSetAttribute(gemm3<true>,  cudaFuncAttributeMaxDynamicSharedMemorySize, SMEM_REQ);
    cudaFuncSetAttribute(gemm3<false>, cudaFuncAttributeMaxDynamicSharedMemorySize, SMEM_REQ);
    cudaFuncSetAttribute(attn_tc,      cudaFuncAttributeMaxDynamicSharedMemorySize, AT_SMEM);

    prep_h<<<MTOT, 384>>>(X, STE);
    prep_w<<<1536 + 512, 384>>>(Wq, Wk, Wv, Wo);

    // QKV: grid (z*4+ntile, mtile) — z-adjacent CTAs reuse the A m-tile in L2
    gemm3<true><<<dim3(12, 512), 128, SMEM_REQ>>>(bq, bk, bv, nullptr);
    attn_tc<<<dim3(KH, NN, BB), 256, AT_SMEM>>>();
    gemm3<false><<<dim3(4, 512), 128, SMEM_REQ>>>(bo, bo, bo, out);
}